// round 2
// baseline (speedup 1.0000x reference)
#include <cuda_runtime.h>

#define Bc 4
#define Nc 2048
#define Cc 256
#define Hc 8
#define DHc 32
#define SCALEF 0.17677669529663687f   // 32^-0.5

// ---- scratch (static device allocations; no cudaMalloc allowed) ----
__device__ float g_q[Bc*Hc*Nc*DHc];     // [B,H,N,Dh]
__device__ float g_k[Bc*Hc*Nc*DHc];
__device__ float g_v[Bc*Hc*Nc*DHc];
__device__ float g_x[Bc*Nc*Cc];         // attention output, [B*N, C]
__device__ float g_rmax[Bc*Nc];         // 1 / max_k mask[b,k,q]

// ---------------------------------------------------------------------------
// Kernel 0: reciprocal of column-max of the mask. mask is [B, Nk, Nq];
// reference normalizes over Nk (axis=1) per (b, q).
// ---------------------------------------------------------------------------
__global__ void __launch_bounds__(256) rmax_kernel(const float* __restrict__ mask)
{
    int i = blockIdx.x * 256 + threadIdx.x;          // i in [0, B*N)
    int b = i >> 11;
    int q = i & (Nc - 1);
    const float* mc = mask + (size_t)b * Nc * Nc + q;
    float mx = 0.f;
#pragma unroll 8
    for (int k = 0; k < Nc; k++)
        mx = fmaxf(mx, mc[(size_t)k * Nc]);          // coalesced across q
    g_rmax[i] = 1.f / mx;
}

// ---------------------------------------------------------------------------
// Kernel 1: QKV projection.  out = X @ W^T + b, X=[8192,256], W=[256,256].
// 128x128 block tile, 8x8 micro tile per thread, k-step 8, smem in [k][m]
// layout so micro-tile fragments load as LDS.128.
// Writes directly in [B,H,N,Dh] layout.
// ---------------------------------------------------------------------------
__global__ void __launch_bounds__(256) qkv_kernel(
    const float* __restrict__ X,
    const float* __restrict__ Wq, const float* __restrict__ Wk, const float* __restrict__ Wv,
    const float* __restrict__ bq, const float* __restrict__ bk, const float* __restrict__ bv)
{
    __shared__ float As[8][132];
    __shared__ float Bs[8][132];

    const float* W; const float* bias; float* out;
    if (blockIdx.z == 0)      { W = Wq; bias = bq; out = g_q; }
    else if (blockIdx.z == 1) { W = Wk; bias = bk; out = g_k; }
    else                      { W = Wv; bias = bv; out = g_v; }

    int m0 = blockIdx.x * 128;
    int n0 = blockIdx.y * 128;
    int tid = threadIdx.x;
    int ty = tid >> 4, tx = tid & 15;
    int lr = tid >> 1;            // 0..127 : row within tile for staging
    int lf = (tid & 1) * 4;       // 0 or 4 : k-offset within 8-wide slab

    float acc[8][8];
#pragma unroll
    for (int i = 0; i < 8; i++)
#pragma unroll
        for (int j = 0; j < 8; j++) acc[i][j] = 0.f;

    for (int k0 = 0; k0 < Cc; k0 += 8) {
        float4 xa = *(const float4*)(X + (size_t)(m0 + lr) * Cc + k0 + lf);
        float4 wb = *(const float4*)(W + (size_t)(n0 + lr) * Cc + k0 + lf);
        __syncthreads();
        As[lf + 0][lr] = xa.x; As[lf + 1][lr] = xa.y; As[lf + 2][lr] = xa.z; As[lf + 3][lr] = xa.w;
        Bs[lf + 0][lr] = wb.x; Bs[lf + 1][lr] = wb.y; Bs[lf + 2][lr] = wb.z; Bs[lf + 3][lr] = wb.w;
        __syncthreads();
#pragma unroll
        for (int kk = 0; kk < 8; kk++) {
            float a[8], bb[8];
            *(float4*)(a)      = *(const float4*)&As[kk][ty * 8];
            *(float4*)(a + 4)  = *(const float4*)&As[kk][ty * 8 + 4];
            *(float4*)(bb)     = *(const float4*)&Bs[kk][tx * 8];
            *(float4*)(bb + 4) = *(const float4*)&Bs[kk][tx * 8 + 4];
#pragma unroll
            for (int i = 0; i < 8; i++)
#pragma unroll
                for (int j = 0; j < 8; j++)
                    acc[i][j] += a[i] * bb[j];
        }
    }

#pragma unroll
    for (int i = 0; i < 8; i++) {
        int m = m0 + ty * 8 + i;
        int b = m >> 11, nr = m & (Nc - 1);
#pragma unroll
        for (int j = 0; j < 8; j++) {
            int n = n0 + tx * 8 + j;
            int h = n >> 5, d = n & 31;
            out[((size_t)(b * Hc + h) * Nc + nr) * DHc + d] = acc[i][j] + bias[n];
        }
    }
}

// ---------------------------------------------------------------------------
// Kernel 2: attention. One block = (b, h, 16 query rows). 256 threads.
// Phase 1: logits[16][2048] in smem (K rows held in registers per thread).
// Phase 2: exact softmax per row; write attn_vis (pre-mask); multiply the
//          normalized mask into the smem probabilities.
// Phase 3: AV with V chunks staged through smem; write x[B*N, C].
// Smem: 16*2048 (logits) + 16*32 (Q) + 256*32 (V stage) floats = 165888 B.
// ---------------------------------------------------------------------------
__global__ void __launch_bounds__(256) attn_kernel(const float* __restrict__ mask,
                                                   float* __restrict__ vis)
{
    extern __shared__ float sm[];
    float* lg = sm;                    // [16][2048]
    float* Qs = sm + 16 * 2048;        // [16][32]
    float* Vs = Qs + 16 * 32;          // [256][32]

    int q0 = blockIdx.x * 16;
    int h  = blockIdx.y;
    int b  = blockIdx.z;
    int bh = b * Hc + h;
    const float* qp = g_q + (size_t)bh * Nc * DHc;
    const float* kp = g_k + (size_t)bh * Nc * DHc;
    const float* vp = g_v + (size_t)bh * Nc * DHc;

    int tid = threadIdx.x;

    // load + pre-scale Q tile
    for (int i = tid; i < 16 * 32; i += 256)
        Qs[i] = qp[(size_t)q0 * DHc + i] * SCALEF;
    __syncthreads();

    // ---- Phase 1: logits ----
    for (int kc = 0; kc < 8; kc++) {
        int k = kc * 256 + tid;
        float kr[32];
        const float4* k4 = (const float4*)(kp + (size_t)k * DHc);
#pragma unroll
        for (int j = 0; j < 8; j++) {
            float4 t = k4[j];
            kr[4*j] = t.x; kr[4*j+1] = t.y; kr[4*j+2] = t.z; kr[4*j+3] = t.w;
        }
#pragma unroll
        for (int q = 0; q < 16; q++) {
            float acc = 0.f;
#pragma unroll
            for (int d = 0; d < 32; d++)
                acc += Qs[q * 32 + d] * kr[d];       // Qs loads are warp-broadcast
            lg[q * 2048 + k] = acc;                  // lanes -> consecutive banks
        }
    }
    __syncthreads();

    // ---- Phase 2: softmax + vis write + mask multiply ----
    int w = tid >> 5, lane = tid & 31;
#pragma unroll
    for (int rr = 0; rr < 2; rr++) {
        int r = w + rr * 8;
        int qg = q0 + r;
        float* row = lg + r * 2048;

        float mx = -1e30f;
        for (int k = lane; k < Nc; k += 32) mx = fmaxf(mx, row[k]);
#pragma unroll
        for (int o = 16; o; o >>= 1) mx = fmaxf(mx, __shfl_xor_sync(0xffffffffu, mx, o));

        float s = 0.f;
        for (int k = lane; k < Nc; k += 32) {
            float e = __expf(row[k] - mx);
            row[k] = e;
            s += e;
        }
#pragma unroll
        for (int o = 16; o; o >>= 1) s += __shfl_xor_sync(0xffffffffu, s, o);
        float inv = 1.f / s;

        float rmx = g_rmax[b * Nc + qg];
        float* visrow = vis + ((size_t)bh * Nc + qg) * Nc;
        const float* mcol = mask + (size_t)b * Nc * Nc + qg;
        for (int k = lane; k < Nc; k += 32) {
            float p = row[k] * inv;
            visrow[k] = p;                           // pre-mask softmax output
            row[k] = p * (mcol[(size_t)k * Nc] * rmx);
        }
    }

    // ---- Phase 3: x = (p*m) @ V ----
    int d  = tid & 31;
    int qq = tid >> 5;                               // rows qq and qq+8
    float acc0 = 0.f, acc1 = 0.f;
    for (int kc = 0; kc < 8; kc++) {
        __syncthreads();                             // done reading Vs / lg from prior phase
        const float4* v4 = (const float4*)(vp + (size_t)(kc * 256) * DHc);
        float4* vs4 = (float4*)Vs;
        for (int j = tid; j < 2048; j += 256) vs4[j] = v4[j];
        __syncthreads();

        const float* p0 = lg + qq * 2048 + kc * 256;
        const float* p1 = lg + (qq + 8) * 2048 + kc * 256;
#pragma unroll 4
        for (int kk = 0; kk < 256; kk++) {
            float vv = Vs[kk * 32 + d];
            acc0 += p0[kk] * vv;                     // broadcast loads
            acc1 += p1[kk] * vv;
        }
    }
    g_x[(size_t)(b * Nc + q0 + qq)     * Cc + h * 32 + d] = acc0;
    g_x[(size_t)(b * Nc + q0 + qq + 8) * Cc + h * 32 + d] = acc1;
}

// ---------------------------------------------------------------------------
// Kernel 3: output projection + residual.
// out[m,n] = query[m,n] + sum_k g_x[m,k]*Wo[n,k] + bo[n]
// ---------------------------------------------------------------------------
__global__ void __launch_bounds__(256) oproj_kernel(
    const float* __restrict__ Wo, const float* __restrict__ bo,
    const float* __restrict__ query, float* __restrict__ out)
{
    __shared__ float As[8][132];
    __shared__ float Bs[8][132];

    int m0 = blockIdx.x * 128;
    int n0 = blockIdx.y * 128;
    int tid = threadIdx.x;
    int ty = tid >> 4, tx = tid & 15;
    int lr = tid >> 1;
    int lf = (tid & 1) * 4;

    float acc[8][8];
#pragma unroll
    for (int i = 0; i < 8; i++)
#pragma unroll
        for (int j = 0; j < 8; j++) acc[i][j] = 0.f;

    for (int k0 = 0; k0 < Cc; k0 += 8) {
        float4 xa = *(const float4*)(g_x + (size_t)(m0 + lr) * Cc + k0 + lf);
        float4 wb = *(const float4*)(Wo  + (size_t)(n0 + lr) * Cc + k0 + lf);
        __syncthreads();
        As[lf + 0][lr] = xa.x; As[lf + 1][lr] = xa.y; As[lf + 2][lr] = xa.z; As[lf + 3][lr] = xa.w;
        Bs[lf + 0][lr] = wb.x; Bs[lf + 1][lr] = wb.y; Bs[lf + 2][lr] = wb.z; Bs[lf + 3][lr] = wb.w;
        __syncthreads();
#pragma unroll
        for (int kk = 0; kk < 8; kk++) {
            float a[8], bb[8];
            *(float4*)(a)      = *(const float4*)&As[kk][ty * 8];
            *(float4*)(a + 4)  = *(const float4*)&As[kk][ty * 8 + 4];
            *(float4*)(bb)     = *(const float4*)&Bs[kk][tx * 8];
            *(float4*)(bb + 4) = *(const float4*)&Bs[kk][tx * 8 + 4];
#pragma unroll
            for (int i = 0; i < 8; i++)
#pragma unroll
                for (int j = 0; j < 8; j++)
                    acc[i][j] += a[i] * bb[j];
        }
    }

#pragma unroll
    for (int i = 0; i < 8; i++) {
        int m = m0 + ty * 8 + i;
#pragma unroll
        for (int j = 0; j < 8; j++) {
            int n = n0 + tx * 8 + j;
            out[(size_t)m * Cc + n] = acc[i][j] + query[(size_t)m * Cc + n] + bo[n];
        }
    }
}

// ---------------------------------------------------------------------------
extern "C" void kernel_launch(void* const* d_in, const int* in_sizes, int n_in,
                              void* d_out, int out_size)
{
    const float* query = (const float*)d_in[0];
    const float* mask  = (const float*)d_in[1];
    const float* Wq = (const float*)d_in[2];
    const float* bq = (const float*)d_in[3];
    const float* Wk = (const float*)d_in[4];
    const float* bk = (const float*)d_in[5];
    const float* Wv = (const float*)d_in[6];
    const float* bv = (const float*)d_in[7];
    const float* Wo = (const float*)d_in[8];
    const float* bo = (const float*)d_in[9];

    float* out_query = (float*)d_out;                       // [B,N,C]
    float* vis       = out_query + (size_t)Bc * Nc * Cc;    // [B,H,N,N]

    rmax_kernel<<<(Bc * Nc) / 256, 256>>>(mask);

    dim3 gq((Bc * Nc) / 128, Cc / 128, 3);
    qkv_kernel<<<gq, 256>>>(query, Wq, Wk, Wv, bq, bk, bv);

    size_t smem = (size_t)(16 * 2048 + 16 * 32 + 256 * 32) * sizeof(float); // 165888 B
    cudaFuncSetAttribute(attn_kernel, cudaFuncAttributeMaxDynamicSharedMemorySize, (int)smem);
    dim3 ga(Nc / 16, Hc, Bc);
    attn_kernel<<<ga, 256, smem>>>(mask, vis);

    dim3 go((Bc * Nc) / 128, Cc / 128);
    oproj_kernel<<<go, 256>>>(Wo, bo, query, out_query);
}

// round 3
// speedup vs baseline: 1.2495x; 1.2495x over previous
#include <cuda_runtime.h>

#define Bc 4
#define Nc 2048
#define Cc 256
#define Hc 8
#define DHc 32
#define SCALEF 0.17677669529663687f   // 32^-0.5

// ---- scratch (static device allocations; no cudaMalloc allowed) ----
__device__ float g_q[Bc*Hc*Nc*DHc];     // [B,H,N,Dh]
__device__ float g_k[Bc*Hc*Nc*DHc];
__device__ float g_v[Bc*Hc*Nc*DHc];
__device__ float g_x[Bc*Nc*Cc];         // attention output, [B*N, C]
__device__ float g_rmax[Bc*Nc];         // 1 / max_k mask[b,k,q]

// ---------------------------------------------------------------------------
// Kernel 0: reciprocal of column-max of the mask. mask is [B, Nk, Nq];
// reference normalizes over Nk (axis=1) per (b, q).
// ---------------------------------------------------------------------------
__global__ void __launch_bounds__(256) rmax_kernel(const float* __restrict__ mask)
{
    int i = blockIdx.x * 256 + threadIdx.x;          // i in [0, B*N)
    int b = i >> 11;
    int q = i & (Nc - 1);
    const float* mc = mask + (size_t)b * Nc * Nc + q;
    float mx = 0.f;
#pragma unroll 8
    for (int k = 0; k < Nc; k++)
        mx = fmaxf(mx, mc[(size_t)k * Nc]);          // coalesced across q
    g_rmax[i] = 1.f / mx;
}

// ---------------------------------------------------------------------------
// Kernel 1: QKV projection.  out = X @ W^T + b, X=[8192,256], W=[256,256].
// ---------------------------------------------------------------------------
__global__ void __launch_bounds__(256) qkv_kernel(
    const float* __restrict__ X,
    const float* __restrict__ Wq, const float* __restrict__ Wk, const float* __restrict__ Wv,
    const float* __restrict__ bq, const float* __restrict__ bk, const float* __restrict__ bv)
{
    __shared__ float As[8][132];
    __shared__ float Bs[8][132];

    const float* W; const float* bias; float* out;
    if (blockIdx.z == 0)      { W = Wq; bias = bq; out = g_q; }
    else if (blockIdx.z == 1) { W = Wk; bias = bk; out = g_k; }
    else                      { W = Wv; bias = bv; out = g_v; }

    int m0 = blockIdx.x * 128;
    int n0 = blockIdx.y * 128;
    int tid = threadIdx.x;
    int ty = tid >> 4, tx = tid & 15;
    int lr = tid >> 1;
    int lf = (tid & 1) * 4;

    float acc[8][8];
#pragma unroll
    for (int i = 0; i < 8; i++)
#pragma unroll
        for (int j = 0; j < 8; j++) acc[i][j] = 0.f;

    for (int k0 = 0; k0 < Cc; k0 += 8) {
        float4 xa = *(const float4*)(X + (size_t)(m0 + lr) * Cc + k0 + lf);
        float4 wb = *(const float4*)(W + (size_t)(n0 + lr) * Cc + k0 + lf);
        __syncthreads();
        As[lf + 0][lr] = xa.x; As[lf + 1][lr] = xa.y; As[lf + 2][lr] = xa.z; As[lf + 3][lr] = xa.w;
        Bs[lf + 0][lr] = wb.x; Bs[lf + 1][lr] = wb.y; Bs[lf + 2][lr] = wb.z; Bs[lf + 3][lr] = wb.w;
        __syncthreads();
#pragma unroll
        for (int kk = 0; kk < 8; kk++) {
            float a[8], bb[8];
            *(float4*)(a)      = *(const float4*)&As[kk][ty * 8];
            *(float4*)(a + 4)  = *(const float4*)&As[kk][ty * 8 + 4];
            *(float4*)(bb)     = *(const float4*)&Bs[kk][tx * 8];
            *(float4*)(bb + 4) = *(const float4*)&Bs[kk][tx * 8 + 4];
#pragma unroll
            for (int i = 0; i < 8; i++)
#pragma unroll
                for (int j = 0; j < 8; j++)
                    acc[i][j] += a[i] * bb[j];
        }
    }

#pragma unroll
    for (int i = 0; i < 8; i++) {
        int m = m0 + ty * 8 + i;
        int b = m >> 11, nr = m & (Nc - 1);
#pragma unroll
        for (int j = 0; j < 8; j++) {
            int n = n0 + tx * 8 + j;
            int h = n >> 5, d = n & 31;
            out[((size_t)(b * Hc + h) * Nc + nr) * DHc + d] = acc[i][j] + bias[n];
        }
    }
}

// ---------------------------------------------------------------------------
// Kernel 2: attention. One block = (b, h, 16 query rows). 512 threads / 16 warps.
// Phase 1: logits[16][2048] in smem. Phase 2: softmax (1 row per warp) +
// vis write + mask multiply with COALESCED smem-staged mask tiles.
// Phase 3: AV, vectorized (LDS.128 on V, 4-way k-split + shfl reduce).
// Smem: 16*2048 (logits) + 16*32 (Q) + 8192 (stage: V chunk / mask chunk).
// ---------------------------------------------------------------------------
__global__ void __launch_bounds__(512) attn_kernel(const float* __restrict__ mask,
                                                   float* __restrict__ vis)
{
    extern __shared__ float sm[];
    float* lg = sm;                    // [16][2048]
    float* Qs = sm + 16 * 2048;        // [16][32]
    float* St = Qs + 16 * 32;          // stage: V [256][32] or mask [256][17]

    int q0 = blockIdx.x * 16;
    int h  = blockIdx.y;
    int b  = blockIdx.z;
    int bh = b * Hc + h;
    const float* qp = g_q + (size_t)bh * Nc * DHc;
    const float* kp = g_k + (size_t)bh * Nc * DHc;
    const float* vp = g_v + (size_t)bh * Nc * DHc;
    const float* mbase = mask + (size_t)b * Nc * Nc;

    int tid  = threadIdx.x;
    int wid  = tid >> 5;
    int lane = tid & 31;

    // load + pre-scale Q tile
    if (tid < 16 * 32)
        Qs[tid] = qp[(size_t)q0 * DHc + tid] * SCALEF;
    __syncthreads();

    // ---- Phase 1: logits. Thread owns one K column per pass. ----
    for (int kc = 0; kc < 4; kc++) {
        int k = kc * 512 + tid;
        float4 kr[8];
        const float4* k4 = (const float4*)(kp + (size_t)k * DHc);
#pragma unroll
        for (int j = 0; j < 8; j++) kr[j] = k4[j];

        float acc[16];
#pragma unroll
        for (int q = 0; q < 16; q++) acc[q] = 0.f;

#pragma unroll
        for (int d4 = 0; d4 < 8; d4++) {
            float4 kv = kr[d4];
#pragma unroll
            for (int q = 0; q < 16; q++) {
                float4 qv = *(const float4*)&Qs[q * 32 + d4 * 4];   // LDS.128 broadcast
                acc[q] += qv.x * kv.x + qv.y * kv.y + qv.z * kv.z + qv.w * kv.w;
            }
        }
#pragma unroll
        for (int q = 0; q < 16; q++)
            lg[q * 2048 + k] = acc[q];
    }
    __syncthreads();

    // ---- Phase 2: softmax (one row per warp) ----
    {
        float* row = lg + wid * 2048;

        float mx = -1e30f;
        for (int k = lane; k < Nc; k += 32) mx = fmaxf(mx, row[k]);
#pragma unroll
        for (int o = 16; o; o >>= 1) mx = fmaxf(mx, __shfl_xor_sync(0xffffffffu, mx, o));

        float s = 0.f;
        for (int k = lane; k < Nc; k += 32) {
            float e = __expf(row[k] - mx);
            row[k] = e;
            s += e;
        }
#pragma unroll
        for (int o = 16; o; o >>= 1) s += __shfl_xor_sync(0xffffffffu, s, o);
        float inv = 1.f / s;
        float rmx = g_rmax[b * Nc + q0 + wid] * inv;

        float* visrow = vis + ((size_t)bh * Nc + q0 + wid) * Nc;

        // chunked: coalesced mask stage -> broadcast consume
        int skk = tid >> 1;                 // 0..255
        int sc8 = (tid & 1) * 8;            // 0 or 8
        for (int ch = 0; ch < 8; ch++) {
            int k0 = ch * 256;
            // stage mask[b, k0:k0+256, q0:q0+16] -> St[kk*17 + c], fully coalesced LDG.128
            const float* mp = mbase + (size_t)(k0 + skk) * Nc + q0 + sc8;
            float4 a0 = ((const float4*)mp)[0];
            float4 a1 = ((const float4*)mp)[1];
            float* dst = St + skk * 17 + sc8;
            dst[0] = a0.x; dst[1] = a0.y; dst[2] = a0.z; dst[3] = a0.w;
            dst[4] = a1.x; dst[5] = a1.y; dst[6] = a1.z; dst[7] = a1.w;
            __syncthreads();

#pragma unroll
            for (int i = 0; i < 8; i++) {
                int kk = lane + i * 32;
                int k = k0 + kk;
                float p = row[k] * inv;
                visrow[k] = p;                              // pre-mask softmax output
                row[k] = p * St[kk * 17 + wid] * rmx * s;   // == p * m * rmx_orig
            }
            __syncthreads();
        }
    }

    // ---- Phase 3: x = (p*m) @ V.  warp = q row; lane = (kgrp, d4). ----
    {
        int d4   = (lane & 7) * 4;
        int kgrp = lane >> 3;               // 4-way k split
        const float* row = lg + wid * 2048;
        float4 acc = make_float4(0.f, 0.f, 0.f, 0.f);

        for (int kc = 0; kc < 8; kc++) {
            // stage V chunk [256][32]
            const float4* v4 = (const float4*)(vp + (size_t)(kc * 256) * DHc);
            float4* st4 = (float4*)St;
#pragma unroll
            for (int j = 0; j < 4; j++) st4[tid + j * 512] = v4[tid + j * 512];
            __syncthreads();

            const float* prow = row + kc * 256;
#pragma unroll 8
            for (int kk = kgrp; kk < 256; kk += 4) {
                float p = prow[kk];                                   // 4-addr multicast
                float4 vv = *(const float4*)&St[kk * 32 + d4];        // LDS.128
                acc.x += p * vv.x; acc.y += p * vv.y;
                acc.z += p * vv.z; acc.w += p * vv.w;
            }
            __syncthreads();
        }

        // reduce the 4 kgrp partials (lanes 8 apart share d4)
#pragma unroll
        for (int o = 8; o <= 16; o <<= 1) {
            acc.x += __shfl_xor_sync(0xffffffffu, acc.x, o);
            acc.y += __shfl_xor_sync(0xffffffffu, acc.y, o);
            acc.z += __shfl_xor_sync(0xffffffffu, acc.z, o);
            acc.w += __shfl_xor_sync(0xffffffffu, acc.w, o);
        }
        if (kgrp == 0)
            *(float4*)&g_x[(size_t)(b * Nc + q0 + wid) * Cc + h * 32 + d4] = acc;
    }
}

// ---------------------------------------------------------------------------
// Kernel 3: output projection + residual.
// ---------------------------------------------------------------------------
__global__ void __launch_bounds__(256) oproj_kernel(
    const float* __restrict__ Wo, const float* __restrict__ bo,
    const float* __restrict__ query, float* __restrict__ out)
{
    __shared__ float As[8][132];
    __shared__ float Bs[8][132];

    int m0 = blockIdx.x * 128;
    int n0 = blockIdx.y * 128;
    int tid = threadIdx.x;
    int ty = tid >> 4, tx = tid & 15;
    int lr = tid >> 1;
    int lf = (tid & 1) * 4;

    float acc[8][8];
#pragma unroll
    for (int i = 0; i < 8; i++)
#pragma unroll
        for (int j = 0; j < 8; j++) acc[i][j] = 0.f;

    for (int k0 = 0; k0 < Cc; k0 += 8) {
        float4 xa = *(const float4*)(g_x + (size_t)(m0 + lr) * Cc + k0 + lf);
        float4 wb = *(const float4*)(Wo  + (size_t)(n0 + lr) * Cc + k0 + lf);
        __syncthreads();
        As[lf + 0][lr] = xa.x; As[lf + 1][lr] = xa.y; As[lf + 2][lr] = xa.z; As[lf + 3][lr] = xa.w;
        Bs[lf + 0][lr] = wb.x; Bs[lf + 1][lr] = wb.y; Bs[lf + 2][lr] = wb.z; Bs[lf + 3][lr] = wb.w;
        __syncthreads();
#pragma unroll
        for (int kk = 0; kk < 8; kk++) {
            float a[8], bb[8];
            *(float4*)(a)      = *(const float4*)&As[kk][ty * 8];
            *(float4*)(a + 4)  = *(const float4*)&As[kk][ty * 8 + 4];
            *(float4*)(bb)     = *(const float4*)&Bs[kk][tx * 8];
            *(float4*)(bb + 4) = *(const float4*)&Bs[kk][tx * 8 + 4];
#pragma unroll
            for (int i = 0; i < 8; i++)
#pragma unroll
                for (int j = 0; j < 8; j++)
                    acc[i][j] += a[i] * bb[j];
        }
    }

#pragma unroll
    for (int i = 0; i < 8; i++) {
        int m = m0 + ty * 8 + i;
#pragma unroll
        for (int j = 0; j < 8; j++) {
            int n = n0 + tx * 8 + j;
            out[(size_t)m * Cc + n] = acc[i][j] + query[(size_t)m * Cc + n] + bo[n];
        }
    }
}

// ---------------------------------------------------------------------------
extern "C" void kernel_launch(void* const* d_in, const int* in_sizes, int n_in,
                              void* d_out, int out_size)
{
    const float* query = (const float*)d_in[0];
    const float* mask  = (const float*)d_in[1];
    const float* Wq = (const float*)d_in[2];
    const float* bq = (const float*)d_in[3];
    const float* Wk = (const float*)d_in[4];
    const float* bk = (const float*)d_in[5];
    const float* Wv = (const float*)d_in[6];
    const float* bv = (const float*)d_in[7];
    const float* Wo = (const float*)d_in[8];
    const float* bo = (const float*)d_in[9];

    float* out_query = (float*)d_out;                       // [B,N,C]
    float* vis       = out_query + (size_t)Bc * Nc * Cc;    // [B,H,N,N]

    rmax_kernel<<<(Bc * Nc) / 256, 256>>>(mask);

    dim3 gq((Bc * Nc) / 128, Cc / 128, 3);
    qkv_kernel<<<gq, 256>>>(query, Wq, Wk, Wv, bq, bk, bv);

    size_t smem = (size_t)(16 * 2048 + 16 * 32 + 8192) * sizeof(float); // 165888 B
    cudaFuncSetAttribute(attn_kernel, cudaFuncAttributeMaxDynamicSharedMemorySize, (int)smem);
    dim3 ga(Nc / 16, Hc, Bc);
    attn_kernel<<<ga, 512, smem>>>(mask, vis);

    dim3 go((Bc * Nc) / 128, Cc / 128);
    oproj_kernel<<<go, 256>>>(Wo, bo, query, out_query);
}

// round 4
// speedup vs baseline: 1.3617x; 1.0898x over previous
#include <cuda_runtime.h>

#define Bc 4
#define Nc 2048
#define Cc 256
#define Hc 8
#define DHc 32
#define SCALEF 0.17677669529663687f   // 32^-0.5

// ---- scratch (static device allocations) ----
__device__ float g_q [Bc*Hc*Nc*DHc];    // [B,H,N,Dh]
__device__ float g_kt[Bc*Hc*DHc*Nc];    // K TRANSPOSED [B,H,Dh,N]
__device__ float g_v [Bc*Hc*Nc*DHc];    // [B,H,N,Dh]
__device__ float g_x [Bc*Nc*Cc];        // attention output [B*N, C]
__device__ unsigned int g_rmaxb[Bc*Nc]; // max_k mask[b,k,q] as monotone uint bits

// ---------------------------------------------------------------------------
// Kernel 0: column-max of mask via atomicMax on float bits (mask > 0).
// grid (8 qblk, 8 kchunk, B), 256 threads. Idempotent across graph replays.
// ---------------------------------------------------------------------------
__global__ void __launch_bounds__(256) rmax_kernel(const float* __restrict__ mask)
{
    int q  = blockIdx.x * 256 + threadIdx.x;
    int k0 = blockIdx.y * 256;
    int b  = blockIdx.z;
    const float* mc = mask + (size_t)b * Nc * Nc + q;
    float mx = 0.f;
#pragma unroll 8
    for (int k = 0; k < 256; k++)
        mx = fmaxf(mx, mc[(size_t)(k0 + k) * Nc]);     // coalesced across q
    atomicMax(&g_rmaxb[b * Nc + q], __float_as_uint(mx));
}

// ---------------------------------------------------------------------------
// Kernel 1: QKV projection.  out = X @ W^T + b.  K written transposed.
// ---------------------------------------------------------------------------
__global__ void __launch_bounds__(256) qkv_kernel(
    const float* __restrict__ X,
    const float* __restrict__ Wq, const float* __restrict__ Wk, const float* __restrict__ Wv,
    const float* __restrict__ bq, const float* __restrict__ bk, const float* __restrict__ bv)
{
    __shared__ float As[8][132];
    __shared__ float Bs[8][132];

    const float* W; const float* bias;
    if (blockIdx.z == 0)      { W = Wq; bias = bq; }
    else if (blockIdx.z == 1) { W = Wk; bias = bk; }
    else                      { W = Wv; bias = bv; }

    int m0 = blockIdx.x * 128;
    int n0 = blockIdx.y * 128;
    int tid = threadIdx.x;
    int ty = tid >> 4, tx = tid & 15;
    int lr = tid >> 1;
    int lf = (tid & 1) * 4;

    float acc[8][8];
#pragma unroll
    for (int i = 0; i < 8; i++)
#pragma unroll
        for (int j = 0; j < 8; j++) acc[i][j] = 0.f;

    for (int k0 = 0; k0 < Cc; k0 += 8) {
        float4 xa = *(const float4*)(X + (size_t)(m0 + lr) * Cc + k0 + lf);
        float4 wb = *(const float4*)(W + (size_t)(n0 + lr) * Cc + k0 + lf);
        __syncthreads();
        As[lf + 0][lr] = xa.x; As[lf + 1][lr] = xa.y; As[lf + 2][lr] = xa.z; As[lf + 3][lr] = xa.w;
        Bs[lf + 0][lr] = wb.x; Bs[lf + 1][lr] = wb.y; Bs[lf + 2][lr] = wb.z; Bs[lf + 3][lr] = wb.w;
        __syncthreads();
#pragma unroll
        for (int kk = 0; kk < 8; kk++) {
            float a[8], bb[8];
            *(float4*)(a)      = *(const float4*)&As[kk][ty * 8];
            *(float4*)(a + 4)  = *(const float4*)&As[kk][ty * 8 + 4];
            *(float4*)(bb)     = *(const float4*)&Bs[kk][tx * 8];
            *(float4*)(bb + 4) = *(const float4*)&Bs[kk][tx * 8 + 4];
#pragma unroll
            for (int i = 0; i < 8; i++)
#pragma unroll
                for (int j = 0; j < 8; j++)
                    acc[i][j] += a[i] * bb[j];
        }
    }

#pragma unroll
    for (int i = 0; i < 8; i++) {
        int m = m0 + ty * 8 + i;
        int b = m >> 11, nr = m & (Nc - 1);
#pragma unroll
        for (int j = 0; j < 8; j++) {
            int n = n0 + tx * 8 + j;
            int h = n >> 5, d = n & 31;
            float val = acc[i][j] + bias[n];
            if (blockIdx.z == 0)
                g_q[((size_t)(b * Hc + h) * Nc + nr) * DHc + d] = val;
            else if (blockIdx.z == 1)
                g_kt[((size_t)(b * Hc + h) * DHc + d) * Nc + nr] = val;   // transposed
            else
                g_v[((size_t)(b * Hc + h) * Nc + nr) * DHc + d] = val;
        }
    }
}

// ---------------------------------------------------------------------------
// Kernel 2: attention. Block = (b, h, 16 q rows). 512 threads / 16 warps.
// Smem: lg[16][2048] + Qs[16][32] + 2 x 32KB stage buffers (double-buffered).
// Phase 1: logits via transposed-K coalesced loads.
// Phase 2: softmax (warp=row) + vis + mask (prefetched, double-buffered).
// Phase 3: AV with 4-rows-per-warp V sharing + 4-way k split + smem combine.
// ---------------------------------------------------------------------------
__global__ void __launch_bounds__(512) attn_kernel(const float* __restrict__ mask,
                                                   float* __restrict__ vis)
{
    extern __shared__ float sm[];
    float* lg = sm;                    // [16][2048]
    float* Qs = sm + 16 * 2048;        // [16][32]
    float* St = Qs + 16 * 32;          // 2 x 8192 floats stage buffers

    int q0 = blockIdx.x * 16;
    int h  = blockIdx.y;
    int b  = blockIdx.z;
    int bh = b * Hc + h;
    const float* qp  = g_q  + (size_t)bh * Nc * DHc;
    const float* ktp = g_kt + (size_t)bh * DHc * Nc;
    const float* vp  = g_v  + (size_t)bh * Nc * DHc;
    const float* mbase = mask + (size_t)b * Nc * Nc;

    int tid  = threadIdx.x;
    int wid  = tid >> 5;
    int lane = tid & 31;

    // load + pre-scale Q tile (512 threads == 16*32 elements)
    Qs[tid] = qp[(size_t)q0 * DHc + tid] * SCALEF;
    __syncthreads();

    // ---- Phase 1: logits, K read from transposed layout (coalesced) ----
    for (int kc = 0; kc < 4; kc++) {
        int k = kc * 512 + tid;
        float kr[32];
#pragma unroll
        for (int d = 0; d < 32; d++)
            kr[d] = ktp[(size_t)d * Nc + k];           // 1 line per warp-instr

        float acc[16];
#pragma unroll
        for (int q = 0; q < 16; q++) acc[q] = 0.f;

#pragma unroll
        for (int d4 = 0; d4 < 8; d4++) {
#pragma unroll
            for (int q = 0; q < 16; q++) {
                float4 qv = *(const float4*)&Qs[q * 32 + d4 * 4];  // broadcast
                acc[q] += qv.x * kr[d4*4] + qv.y * kr[d4*4+1]
                        + qv.z * kr[d4*4+2] + qv.w * kr[d4*4+3];
            }
        }
#pragma unroll
        for (int q = 0; q < 16; q++)
            lg[q * 2048 + k] = acc[q];
    }
    __syncthreads();

    // ---- Phase 2: softmax (warp = row) + vis + mask, double-buffered ----
    {
        float* row = lg + wid * 2048;

        float mx = -1e30f;
        for (int k = lane; k < Nc; k += 32) mx = fmaxf(mx, row[k]);
#pragma unroll
        for (int o = 16; o; o >>= 1) mx = fmaxf(mx, __shfl_xor_sync(0xffffffffu, mx, o));

        float s = 0.f;
        for (int k = lane; k < Nc; k += 32) {
            float e = __expf(row[k] - mx);
            row[k] = e;
            s += e;
        }
#pragma unroll
        for (int o = 16; o; o >>= 1) s += __shfl_xor_sync(0xffffffffu, s, o);
        float inv = 1.f / s;
        float rmx = 1.f / __uint_as_float(g_rmaxb[b * Nc + q0 + wid]);

        float* visrow = vis + ((size_t)bh * Nc + q0 + wid) * Nc;

        int skk = tid >> 1;                 // 0..255
        int sc8 = (tid & 1) * 8;            // 0 or 8
        const float* mp = mbase + (size_t)skk * Nc + q0 + sc8;
        float4 a0 = ((const float4*)mp)[0];
        float4 a1 = ((const float4*)mp)[1];

        for (int ch = 0; ch < 8; ch++) {
            float* Sb = St + (ch & 1) * 8192;
            float* dst = Sb + skk * 17 + sc8;
            dst[0] = a0.x; dst[1] = a0.y; dst[2] = a0.z; dst[3] = a0.w;
            dst[4] = a1.x; dst[5] = a1.y; dst[6] = a1.z; dst[7] = a1.w;
            if (ch < 7) {                   // prefetch next chunk (hidden by consume)
                const float* mn = mbase + (size_t)((ch + 1) * 256 + skk) * Nc + q0 + sc8;
                a0 = ((const float4*)mn)[0];
                a1 = ((const float4*)mn)[1];
            }
            __syncthreads();
#pragma unroll
            for (int i = 0; i < 8; i++) {
                int kk = lane + i * 32;
                int k = ch * 256 + kk;
                float p = row[k] * inv;
                visrow[k] = p;                          // pre-mask softmax output
                row[k] = p * Sb[kk * 17 + wid] * rmx;   // post-mask prob
            }
            // no trailing sync: next STS targets the other buffer; the
            // following iteration's barrier orders reuse of this one.
        }
    }

    // ---- Phase 3: x = P @ V.  warp = (4 q rows, k-quarter); lane = (kg, d4) ----
    {
        int rbase = (wid & 3) * 4;          // rows rbase..rbase+3
        int kq    = wid >> 2;               // k-quarter (64 kk per chunk)
        int d4    = (lane & 7) * 4;
        int kg    = lane >> 3;              // 0..3

        float4 acc[4];
#pragma unroll
        for (int r = 0; r < 4; r++) acc[r] = make_float4(0.f, 0.f, 0.f, 0.f);

        const float4* v4 = (const float4*)vp;
        float4 vr[4];
#pragma unroll
        for (int j = 0; j < 4; j++) vr[j] = v4[tid + j * 512];

        for (int ch = 0; ch < 8; ch++) {
            float* Vb = St + (ch & 1) * 8192;
#pragma unroll
            for (int j = 0; j < 4; j++) ((float4*)Vb)[tid + j * 512] = vr[j];
            if (ch < 7) {
                const float4* vn = (const float4*)(vp + (size_t)(ch + 1) * 256 * DHc);
#pragma unroll
                for (int j = 0; j < 4; j++) vr[j] = vn[tid + j * 512];
            }
            __syncthreads();   // also orders phase-2 lg writes before first read

            const float* pb = lg + ch * 256 + kq * 64;
#pragma unroll 4
            for (int g = 0; g < 16; g++) {
                int kk = kq * 64 + g * 4 + kg;
                float4 vv = *(const float4*)&Vb[kk * 32 + d4];
#pragma unroll
                for (int r = 0; r < 4; r++) {
                    float4 p4 = *(const float4*)&pb[(rbase + r) * 2048 + g * 4]; // broadcast
                    float p = (kg == 0) ? p4.x : (kg == 1) ? p4.y : (kg == 2) ? p4.z : p4.w;
                    acc[r].x += p * vv.x; acc[r].y += p * vv.y;
                    acc[r].z += p * vv.z; acc[r].w += p * vv.w;
                }
            }
        }

        // reduce the 4 kg partials within the warp (lanes 8/16 apart share d4)
#pragma unroll
        for (int r = 0; r < 4; r++) {
#pragma unroll
            for (int o = 8; o <= 16; o <<= 1) {
                acc[r].x += __shfl_xor_sync(0xffffffffu, acc[r].x, o);
                acc[r].y += __shfl_xor_sync(0xffffffffu, acc[r].y, o);
                acc[r].z += __shfl_xor_sync(0xffffffffu, acc[r].z, o);
                acc[r].w += __shfl_xor_sync(0xffffffffu, acc[r].w, o);
            }
        }

        // stash per-kq partials in St[0..2048): [kq][16 rows][32 d]
        if (lane < 8) {
#pragma unroll
            for (int r = 0; r < 4; r++)
                *(float4*)&St[(kq * 16 + rbase + r) * 32 + d4] = acc[r];
        }
        __syncthreads();

        // combine 4 k-quarters and write x
        int r = tid >> 5, d = tid & 31;
        float x = St[(r) * 32 + d] + St[(16 + r) * 32 + d]
                + St[(32 + r) * 32 + d] + St[(48 + r) * 32 + d];
        g_x[((size_t)(b * Nc + q0 + r)) * Cc + h * 32 + d] = x;
    }
}

// ---------------------------------------------------------------------------
// Kernel 3: output projection + residual.
// ---------------------------------------------------------------------------
__global__ void __launch_bounds__(256) oproj_kernel(
    const float* __restrict__ Wo, const float* __restrict__ bo,
    const float* __restrict__ query, float* __restrict__ out)
{
    __shared__ float As[8][132];
    __shared__ float Bs[8][132];

    int m0 = blockIdx.x * 128;
    int n0 = blockIdx.y * 128;
    int tid = threadIdx.x;
    int ty = tid >> 4, tx = tid & 15;
    int lr = tid >> 1;
    int lf = (tid & 1) * 4;

    float acc[8][8];
#pragma unroll
    for (int i = 0; i < 8; i++)
#pragma unroll
        for (int j = 0; j < 8; j++) acc[i][j] = 0.f;

    for (int k0 = 0; k0 < Cc; k0 += 8) {
        float4 xa = *(const float4*)(g_x + (size_t)(m0 + lr) * Cc + k0 + lf);
        float4 wb = *(const float4*)(Wo  + (size_t)(n0 + lr) * Cc + k0 + lf);
        __syncthreads();
        As[lf + 0][lr] = xa.x; As[lf + 1][lr] = xa.y; As[lf + 2][lr] = xa.z; As[lf + 3][lr] = xa.w;
        Bs[lf + 0][lr] = wb.x; Bs[lf + 1][lr] = wb.y; Bs[lf + 2][lr] = wb.z; Bs[lf + 3][lr] = wb.w;
        __syncthreads();
#pragma unroll
        for (int kk = 0; kk < 8; kk++) {
            float a[8], bb[8];
            *(float4*)(a)      = *(const float4*)&As[kk][ty * 8];
            *(float4*)(a + 4)  = *(const float4*)&As[kk][ty * 8 + 4];
            *(float4*)(bb)     = *(const float4*)&Bs[kk][tx * 8];
            *(float4*)(bb + 4) = *(const float4*)&Bs[kk][tx * 8 + 4];
#pragma unroll
            for (int i = 0; i < 8; i++)
#pragma unroll
                for (int j = 0; j < 8; j++)
                    acc[i][j] += a[i] * bb[j];
        }
    }

#pragma unroll
    for (int i = 0; i < 8; i++) {
        int m = m0 + ty * 8 + i;
#pragma unroll
        for (int j = 0; j < 8; j++) {
            int n = n0 + tx * 8 + j;
            out[(size_t)m * Cc + n] = acc[i][j] + query[(size_t)m * Cc + n] + bo[n];
        }
    }
}

// ---------------------------------------------------------------------------
extern "C" void kernel_launch(void* const* d_in, const int* in_sizes, int n_in,
                              void* d_out, int out_size)
{
    const float* query = (const float*)d_in[0];
    const float* mask  = (const float*)d_in[1];
    const float* Wq = (const float*)d_in[2];
    const float* bq = (const float*)d_in[3];
    const float* Wk = (const float*)d_in[4];
    const float* bk = (const float*)d_in[5];
    const float* Wv = (const float*)d_in[6];
    const float* bv = (const float*)d_in[7];
    const float* Wo = (const float*)d_in[8];
    const float* bo = (const float*)d_in[9];

    float* out_query = (float*)d_out;                       // [B,N,C]
    float* vis       = out_query + (size_t)Bc * Nc * Cc;    // [B,H,N,N]

    dim3 gr(Nc / 256, Nc / 256, Bc);
    rmax_kernel<<<gr, 256>>>(mask);

    dim3 gq((Bc * Nc) / 128, Cc / 128, 3);
    qkv_kernel<<<gq, 256>>>(query, Wq, Wk, Wv, bq, bk, bv);

    size_t smem = (size_t)(16 * 2048 + 16 * 32 + 2 * 8192) * sizeof(float); // 198656 B
    cudaFuncSetAttribute(attn_kernel, cudaFuncAttributeMaxDynamicSharedMemorySize, (int)smem);
    dim3 ga(Nc / 16, Hc, Bc);
    attn_kernel<<<ga, 512, smem>>>(mask, vis);

    dim3 go((Bc * Nc) / 128, Cc / 128);
    oproj_kernel<<<go, 256>>>(Wo, bo, query, out_query);
}

// round 5
// speedup vs baseline: 2.2123x; 1.6246x over previous
#include <cuda_runtime.h>
#include <cstdint>

#define Bc 4
#define Nc 2048
#define Cc 256
#define Hc 8
#define DHc 32
#define SCALEF 0.17677669529663687f   // 32^-0.5
#define LGS 2056                      // lg row stride (floats)
#define QSS 36                        // Q tile row stride

// ---- scratch (static device allocations) ----
__device__ float g_q [Bc*Hc*Nc*DHc];    // [B,H,N,Dh]
__device__ float g_kt[Bc*Hc*DHc*Nc];    // K transposed [B,H,Dh,N]
__device__ float g_v [Bc*Hc*Nc*DHc];    // [B,H,N,Dh]
__device__ float g_x [Bc*Nc*Cc];        // attention output [B*N, C]
__device__ unsigned int g_rmaxb[Bc*Nc]; // max_k mask[b,k,q] as monotone uint bits

// ---- tf32 helpers ----
__device__ __forceinline__ float to_tf32(float x) {
    unsigned u;
    asm("cvt.rna.tf32.f32 %0, %1;" : "=r"(u) : "f"(x));
    return __uint_as_float(u);
}
__device__ __forceinline__ void mma8(float& d0, float& d1, float& d2, float& d3,
                                     unsigned a0, unsigned a1, unsigned a2, unsigned a3,
                                     unsigned b0, unsigned b1) {
    asm volatile(
        "mma.sync.aligned.m16n8k8.row.col.f32.tf32.tf32.f32 "
        "{%0,%1,%2,%3},{%4,%5,%6,%7},{%8,%9},{%0,%1,%2,%3};"
        : "+f"(d0), "+f"(d1), "+f"(d2), "+f"(d3)
        : "r"(a0), "r"(a1), "r"(a2), "r"(a3), "r"(b0), "r"(b1));
}

// ---------------------------------------------------------------------------
// Kernel 0: column-max of mask via atomicMax on float bits (mask > 0).
// ---------------------------------------------------------------------------
__global__ void __launch_bounds__(256) rmax_kernel(const float* __restrict__ mask)
{
    int q  = blockIdx.x * 256 + threadIdx.x;
    int k0 = blockIdx.y * 256;
    int b  = blockIdx.z;
    const float* mc = mask + (size_t)b * Nc * Nc + q;
    float mx = 0.f;
#pragma unroll 8
    for (int k = 0; k < 256; k++)
        mx = fmaxf(mx, mc[(size_t)(k0 + k) * Nc]);
    atomicMax(&g_rmaxb[b * Nc + q], __float_as_uint(mx));
}

// ---------------------------------------------------------------------------
// Kernel 1: QKV projection.  out = X @ W^T + b.  K written transposed.
// ---------------------------------------------------------------------------
__global__ void __launch_bounds__(256) qkv_kernel(
    const float* __restrict__ X,
    const float* __restrict__ Wq, const float* __restrict__ Wk, const float* __restrict__ Wv,
    const float* __restrict__ bq, const float* __restrict__ bk, const float* __restrict__ bv)
{
    __shared__ float As[8][132];
    __shared__ float Bs[8][132];

    const float* W; const float* bias;
    if (blockIdx.z == 0)      { W = Wq; bias = bq; }
    else if (blockIdx.z == 1) { W = Wk; bias = bk; }
    else                      { W = Wv; bias = bv; }

    int m0 = blockIdx.x * 128;
    int n0 = blockIdx.y * 128;
    int tid = threadIdx.x;
    int ty = tid >> 4, tx = tid & 15;
    int lr = tid >> 1;
    int lf = (tid & 1) * 4;

    float acc[8][8];
#pragma unroll
    for (int i = 0; i < 8; i++)
#pragma unroll
        for (int j = 0; j < 8; j++) acc[i][j] = 0.f;

    for (int k0 = 0; k0 < Cc; k0 += 8) {
        float4 xa = *(const float4*)(X + (size_t)(m0 + lr) * Cc + k0 + lf);
        float4 wb = *(const float4*)(W + (size_t)(n0 + lr) * Cc + k0 + lf);
        __syncthreads();
        As[lf + 0][lr] = xa.x; As[lf + 1][lr] = xa.y; As[lf + 2][lr] = xa.z; As[lf + 3][lr] = xa.w;
        Bs[lf + 0][lr] = wb.x; Bs[lf + 1][lr] = wb.y; Bs[lf + 2][lr] = wb.z; Bs[lf + 3][lr] = wb.w;
        __syncthreads();
#pragma unroll
        for (int kk = 0; kk < 8; kk++) {
            float a[8], bb[8];
            *(float4*)(a)      = *(const float4*)&As[kk][ty * 8];
            *(float4*)(a + 4)  = *(const float4*)&As[kk][ty * 8 + 4];
            *(float4*)(bb)     = *(const float4*)&Bs[kk][tx * 8];
            *(float4*)(bb + 4) = *(const float4*)&Bs[kk][tx * 8 + 4];
#pragma unroll
            for (int i = 0; i < 8; i++)
#pragma unroll
                for (int j = 0; j < 8; j++)
                    acc[i][j] += a[i] * bb[j];
        }
    }

#pragma unroll
    for (int i = 0; i < 8; i++) {
        int m = m0 + ty * 8 + i;
        int b = m >> 11, nr = m & (Nc - 1);
#pragma unroll
        for (int j = 0; j < 8; j++) {
            int n = n0 + tx * 8 + j;
            int h = n >> 5, d = n & 31;
            float val = acc[i][j] + bias[n];
            if (blockIdx.z == 0)
                g_q[((size_t)(b * Hc + h) * Nc + nr) * DHc + d] = val;
            else if (blockIdx.z == 1)
                g_kt[((size_t)(b * Hc + h) * DHc + d) * Nc + nr] = val;
            else
                g_v[((size_t)(b * Hc + h) * Nc + nr) * DHc + d] = val;
        }
    }
}

// ---------------------------------------------------------------------------
// Kernel 2: attention with tf32 mma.sync (m16n8k8).
// Block = (b, h, 16 q rows). 512 threads / 16 warps.
// Smem: lg[16][LGS] (logits/P) + Qs[16][QSS] + St (stage, 16640 floats).
// Phase 1: S = Q K^T via MMA, K staged per 512-k chunk (stride 520).
// Phase 2: softmax (warp = row) + vis + mask multiply (tf32-rounded P).
// Phase 3: x = P V via MMA, V staged per 256-k chunk (stride 40).
// ---------------------------------------------------------------------------
__global__ void __launch_bounds__(512) attn_kernel(const float* __restrict__ mask,
                                                   float* __restrict__ vis)
{
    extern __shared__ float sm[];
    float* lg = sm;                       // [16][LGS]
    float* Qs = sm + 16 * LGS;            // [16][QSS]
    float* St = Qs + 16 * QSS;            // 16640 floats stage area

    int q0 = blockIdx.x * 16;
    int h  = blockIdx.y;
    int b  = blockIdx.z;
    int bh = b * Hc + h;
    const float* qp  = g_q  + (size_t)bh * Nc * DHc;
    const float* ktp = g_kt + (size_t)bh * DHc * Nc;
    const float* vp  = g_v  + (size_t)bh * Nc * DHc;
    const float* mbase = mask + (size_t)b * Nc * Nc;

    int tid  = threadIdx.x;
    int wid  = tid >> 5;
    int lane = tid & 31;
    int grp  = lane >> 2;                 // 0..7
    int tig  = lane & 3;                  // 0..3

    // stage Q tile (tf32-rounded, pre-scaled)
    {
        int q = tid >> 5, d = tid & 31;
        Qs[q * QSS + d] = to_tf32(qp[(size_t)q0 * DHc + tid] * SCALEF);
    }
    __syncthreads();

    // A fragments of Q (same for every warp): 4 k-steps x 4 regs
    unsigned aq[4][4];
#pragma unroll
    for (int s = 0; s < 4; s++) {
        int dc = s * 8 + tig;
        aq[s][0] = __float_as_uint(Qs[grp * QSS + dc]);
        aq[s][1] = __float_as_uint(Qs[(grp + 8) * QSS + dc]);
        aq[s][2] = __float_as_uint(Qs[grp * QSS + dc + 4]);
        aq[s][3] = __float_as_uint(Qs[(grp + 8) * QSS + dc + 4]);
    }

    // ---- Phase 1: S = Q K^T, 4 chunks of 512 k ----
    for (int c = 0; c < 4; c++) {
        // stage K^T chunk: St[d][kk], stride 520 (float4-aligned, conflict-free frags)
        float4* St4 = (float4*)St;
        const float4* kt4 = (const float4*)ktp;
#pragma unroll
        for (int j = 0; j < 8; j++) {
            int idx = tid + j * 512;           // 4096 float4
            int d   = idx >> 7;                // 0..31
            int kk4 = idx & 127;               // 0..127
            float4 v = kt4[(size_t)d * 512 + c * 128 + kk4];
            v.x = to_tf32(v.x); v.y = to_tf32(v.y);
            v.z = to_tf32(v.z); v.w = to_tf32(v.w);
            St4[d * 130 + kk4] = v;
        }
        __syncthreads();

        // warp handles kk in [wid*32, wid*32+32): 4 n-tiles of 8
#pragma unroll
        for (int nt = 0; nt < 4; nt++) {
            int kb = wid * 32 + nt * 8;
            float d0 = 0.f, d1 = 0.f, d2 = 0.f, d3 = 0.f;
#pragma unroll
            for (int s = 0; s < 4; s++) {
                int dr = s * 8 + tig;
                unsigned b0 = __float_as_uint(St[dr * 520 + kb + grp]);
                unsigned b1 = __float_as_uint(St[(dr + 4) * 520 + kb + grp]);
                mma8(d0, d1, d2, d3, aq[s][0], aq[s][1], aq[s][2], aq[s][3], b0, b1);
            }
            int kg = c * 512 + kb + 2 * tig;
            *(float2*)&lg[grp * LGS + kg]       = make_float2(d0, d1);
            *(float2*)&lg[(grp + 8) * LGS + kg] = make_float2(d2, d3);
        }
        __syncthreads();
    }

    // ---- Phase 2: softmax (warp = row) + vis + mask ----
    {
        float* row = lg + wid * LGS;

        float mx = -1e30f;
        for (int k = lane; k < Nc; k += 32) mx = fmaxf(mx, row[k]);
#pragma unroll
        for (int o = 16; o; o >>= 1) mx = fmaxf(mx, __shfl_xor_sync(0xffffffffu, mx, o));

        float s = 0.f;
        for (int k = lane; k < Nc; k += 32) {
            float e = __expf(row[k] - mx);
            row[k] = e;
            s += e;
        }
#pragma unroll
        for (int o = 16; o; o >>= 1) s += __shfl_xor_sync(0xffffffffu, s, o);
        float inv = 1.f / s;
        float rmx = 1.f / __uint_as_float(g_rmaxb[b * Nc + q0 + wid]);

        float* visrow = vis + ((size_t)bh * Nc + q0 + wid) * Nc;

        int skk = tid >> 1;                 // 0..255
        int sc8 = (tid & 1) * 8;            // 0 or 8
        for (int ch = 0; ch < 8; ch++) {
            // stage mask[b, k0:k0+256, q0:q0+16] -> St[kk*17 + c]
            const float* mp = mbase + (size_t)(ch * 256 + skk) * Nc + q0 + sc8;
            float4 a0 = ((const float4*)mp)[0];
            float4 a1 = ((const float4*)mp)[1];
            float* dst = St + skk * 17 + sc8;
            dst[0] = a0.x; dst[1] = a0.y; dst[2] = a0.z; dst[3] = a0.w;
            dst[4] = a1.x; dst[5] = a1.y; dst[6] = a1.z; dst[7] = a1.w;
            __syncthreads();
#pragma unroll
            for (int i = 0; i < 8; i++) {
                int kk = lane + i * 32;
                int k = ch * 256 + kk;
                float p = row[k] * inv;
                visrow[k] = p;                                  // pre-mask prob
                row[k] = to_tf32(p * St[kk * 17 + wid] * rmx);  // masked, tf32
            }
            __syncthreads();
        }
    }

    // ---- Phase 3: x = P V.  warp = (d-tile, k-quarter). 8 chunks of 256 k ----
    {
        int dt = (wid & 3) * 8;             // d-tile base
        int kq = wid >> 2;                  // k quarter (64 k per chunk)
        float x0 = 0.f, x1 = 0.f, x2 = 0.f, x3 = 0.f;

        for (int c = 0; c < 8; c++) {
            // stage V chunk: St[k][d], stride 40 (float4-aligned)
            float4* St4 = (float4*)St;
            const float4* v4 = (const float4*)(vp + (size_t)c * 256 * DHc);
#pragma unroll
            for (int j = 0; j < 4; j++) {
                int idx = tid + j * 512;        // 2048 float4
                int k   = idx >> 3;
                int d4  = idx & 7;
                float4 v = v4[idx];
                v.x = to_tf32(v.x); v.y = to_tf32(v.y);
                v.z = to_tf32(v.z); v.w = to_tf32(v.w);
                St4[k * 10 + d4] = v;
            }
            __syncthreads();

#pragma unroll
            for (int s2 = 0; s2 < 8; s2++) {
                int kb = kq * 64 + s2 * 8;
                int kg = c * 256 + kb;
                unsigned a0 = __float_as_uint(lg[grp * LGS + kg + tig]);
                unsigned a1 = __float_as_uint(lg[(grp + 8) * LGS + kg + tig]);
                unsigned a2 = __float_as_uint(lg[grp * LGS + kg + tig + 4]);
                unsigned a3 = __float_as_uint(lg[(grp + 8) * LGS + kg + tig + 4]);
                unsigned b0 = __float_as_uint(St[(kb + tig) * 40 + dt + grp]);
                unsigned b1 = __float_as_uint(St[(kb + tig + 4) * 40 + dt + grp]);
                mma8(x0, x1, x2, x3, a0, a1, a2, a3, b0, b1);
            }
            __syncthreads();
        }

        // cross-warp combine over the 4 k-quarters: St[(kq*16 + q)*33 + d]
        St[(kq * 16 + grp) * 33 + dt + 2 * tig]     = x0;
        St[(kq * 16 + grp) * 33 + dt + 2 * tig + 1] = x1;
        St[(kq * 16 + grp + 8) * 33 + dt + 2 * tig]     = x2;
        St[(kq * 16 + grp + 8) * 33 + dt + 2 * tig + 1] = x3;
        __syncthreads();

        int q = tid >> 5, d = tid & 31;
        float x = St[q * 33 + d] + St[(16 + q) * 33 + d]
                + St[(32 + q) * 33 + d] + St[(48 + q) * 33 + d];
        g_x[((size_t)(b * Nc + q0 + q)) * Cc + h * 32 + d] = x;
    }
}

// ---------------------------------------------------------------------------
// Kernel 3: output projection + residual.
// ---------------------------------------------------------------------------
__global__ void __launch_bounds__(256) oproj_kernel(
    const float* __restrict__ Wo, const float* __restrict__ bo,
    const float* __restrict__ query, float* __restrict__ out)
{
    __shared__ float As[8][132];
    __shared__ float Bs[8][132];

    int m0 = blockIdx.x * 128;
    int n0 = blockIdx.y * 128;
    int tid = threadIdx.x;
    int ty = tid >> 4, tx = tid & 15;
    int lr = tid >> 1;
    int lf = (tid & 1) * 4;

    float acc[8][8];
#pragma unroll
    for (int i = 0; i < 8; i++)
#pragma unroll
        for (int j = 0; j < 8; j++) acc[i][j] = 0.f;

    for (int k0 = 0; k0 < Cc; k0 += 8) {
        float4 xa = *(const float4*)(g_x + (size_t)(m0 + lr) * Cc + k0 + lf);
        float4 wb = *(const float4*)(Wo  + (size_t)(n0 + lr) * Cc + k0 + lf);
        __syncthreads();
        As[lf + 0][lr] = xa.x; As[lf + 1][lr] = xa.y; As[lf + 2][lr] = xa.z; As[lf + 3][lr] = xa.w;
        Bs[lf + 0][lr] = wb.x; Bs[lf + 1][lr] = wb.y; Bs[lf + 2][lr] = wb.z; Bs[lf + 3][lr] = wb.w;
        __syncthreads();
#pragma unroll
        for (int kk = 0; kk < 8; kk++) {
            float a[8], bb[8];
            *(float4*)(a)      = *(const float4*)&As[kk][ty * 8];
            *(float4*)(a + 4)  = *(const float4*)&As[kk][ty * 8 + 4];
            *(float4*)(bb)     = *(const float4*)&Bs[kk][tx * 8];
            *(float4*)(bb + 4) = *(const float4*)&Bs[kk][tx * 8 + 4];
#pragma unroll
            for (int i = 0; i < 8; i++)
#pragma unroll
                for (int j = 0; j < 8; j++)
                    acc[i][j] += a[i] * bb[j];
        }
    }

#pragma unroll
    for (int i = 0; i < 8; i++) {
        int m = m0 + ty * 8 + i;
#pragma unroll
        for (int j = 0; j < 8; j++) {
            int n = n0 + tx * 8 + j;
            out[(size_t)m * Cc + n] = acc[i][j] + query[(size_t)m * Cc + n] + bo[n];
        }
    }
}

// ---------------------------------------------------------------------------
extern "C" void kernel_launch(void* const* d_in, const int* in_sizes, int n_in,
                              void* d_out, int out_size)
{
    const float* query = (const float*)d_in[0];
    const float* mask  = (const float*)d_in[1];
    const float* Wq = (const float*)d_in[2];
    const float* bq = (const float*)d_in[3];
    const float* Wk = (const float*)d_in[4];
    const float* bk = (const float*)d_in[5];
    const float* Wv = (const float*)d_in[6];
    const float* bv = (const float*)d_in[7];
    const float* Wo = (const float*)d_in[8];
    const float* bo = (const float*)d_in[9];

    float* out_query = (float*)d_out;                       // [B,N,C]
    float* vis       = out_query + (size_t)Bc * Nc * Cc;    // [B,H,N,N]

    dim3 gr(Nc / 256, Nc / 256, Bc);
    rmax_kernel<<<gr, 256>>>(mask);

    dim3 gq((Bc * Nc) / 128, Cc / 128, 3);
    qkv_kernel<<<gq, 256>>>(query, Wq, Wk, Wv, bq, bk, bv);

    size_t smem = (size_t)(16 * LGS + 16 * QSS + 16640) * sizeof(float); // 200448 B
    cudaFuncSetAttribute(attn_kernel, cudaFuncAttributeMaxDynamicSharedMemorySize, (int)smem);
    dim3 ga(Nc / 16, Hc, Bc);
    attn_kernel<<<ga, 512, smem>>>(mask, vis);

    dim3 go((Bc * Nc) / 128, Cc / 128);
    oproj_kernel<<<go, 256>>>(Wo, bo, query, out_query);
}

// round 6
// speedup vs baseline: 2.4994x; 1.1298x over previous
#include <cuda_runtime.h>
#include <cstdint>

#define Bc 4
#define Nc 2048
#define Cc 256
#define Hc 8
#define DHc 32
#define SCALEF 0.17677669529663687f   // 32^-0.5
#define LGS 2056                      // lg row stride (floats)
#define QSS 36                        // Q tile row stride
#define MSS 260                       // mask stage row stride

// ---- scratch (static device allocations) ----
__device__ float g_q [Bc*Hc*Nc*DHc];    // [B,H,N,Dh]
__device__ float g_kt[Bc*Hc*DHc*Nc];    // K transposed [B,H,Dh,N]
__device__ float g_v [Bc*Hc*Nc*DHc];    // [B,H,N,Dh]
__device__ float g_x [Bc*Nc*Cc];        // attention output [B*N, C]
__device__ unsigned int g_rmaxb[Bc*Nc]; // max_k mask[b,k,q] as monotone uint bits

// ---- tf32 helpers ----
__device__ __forceinline__ float to_tf32(float x) {
    unsigned u;
    asm("cvt.rna.tf32.f32 %0, %1;" : "=r"(u) : "f"(x));
    return __uint_as_float(u);
}
__device__ __forceinline__ void mma8(float& d0, float& d1, float& d2, float& d3,
                                     unsigned a0, unsigned a1, unsigned a2, unsigned a3,
                                     unsigned b0, unsigned b1) {
    asm volatile(
        "mma.sync.aligned.m16n8k8.row.col.f32.tf32.tf32.f32 "
        "{%0,%1,%2,%3},{%4,%5,%6,%7},{%8,%9},{%0,%1,%2,%3};"
        : "+f"(d0), "+f"(d1), "+f"(d2), "+f"(d3)
        : "r"(a0), "r"(a1), "r"(a2), "r"(a3), "r"(b0), "r"(b1));
}

// ---------------------------------------------------------------------------
// Kernel 0: column-max of mask via atomicMax on float bits (mask > 0).
// ---------------------------------------------------------------------------
__global__ void __launch_bounds__(256) rmax_kernel(const float* __restrict__ mask)
{
    int q  = blockIdx.x * 256 + threadIdx.x;
    int k0 = blockIdx.y * 256;
    int b  = blockIdx.z;
    const float* mc = mask + (size_t)b * Nc * Nc + q;
    float mx = 0.f;
#pragma unroll 8
    for (int k = 0; k < 256; k++)
        mx = fmaxf(mx, mc[(size_t)(k0 + k) * Nc]);
    atomicMax(&g_rmaxb[b * Nc + q], __float_as_uint(mx));
}

// ---------------------------------------------------------------------------
// Kernel 1: QKV projection. 128x64 tile, 8x4 microtile (better occupancy).
// K written transposed.
// ---------------------------------------------------------------------------
__global__ void __launch_bounds__(256) qkv_kernel(
    const float* __restrict__ X,
    const float* __restrict__ Wq, const float* __restrict__ Wk, const float* __restrict__ Wv,
    const float* __restrict__ bq, const float* __restrict__ bk, const float* __restrict__ bv)
{
    __shared__ float As[8][132];
    __shared__ float Bs[8][68];

    const float* W; const float* bias;
    if (blockIdx.z == 0)      { W = Wq; bias = bq; }
    else if (blockIdx.z == 1) { W = Wk; bias = bk; }
    else                      { W = Wv; bias = bv; }

    int m0 = blockIdx.x * 128;
    int n0 = blockIdx.y * 64;
    int tid = threadIdx.x;
    int ty = tid >> 4, tx = tid & 15;
    int lr = tid >> 1;
    int lf = (tid & 1) * 4;

    float acc[8][4];
#pragma unroll
    for (int i = 0; i < 8; i++)
#pragma unroll
        for (int j = 0; j < 4; j++) acc[i][j] = 0.f;

    for (int k0 = 0; k0 < Cc; k0 += 8) {
        float4 xa = *(const float4*)(X + (size_t)(m0 + lr) * Cc + k0 + lf);
        float4 wb;
        if (tid < 128)
            wb = *(const float4*)(W + (size_t)(n0 + lr) * Cc + k0 + lf);
        __syncthreads();
        As[lf + 0][lr] = xa.x; As[lf + 1][lr] = xa.y; As[lf + 2][lr] = xa.z; As[lf + 3][lr] = xa.w;
        if (tid < 128) {
            Bs[lf + 0][lr] = wb.x; Bs[lf + 1][lr] = wb.y;
            Bs[lf + 2][lr] = wb.z; Bs[lf + 3][lr] = wb.w;
        }
        __syncthreads();
#pragma unroll
        for (int kk = 0; kk < 8; kk++) {
            float a[8], bb[4];
            *(float4*)(a)      = *(const float4*)&As[kk][ty * 8];
            *(float4*)(a + 4)  = *(const float4*)&As[kk][ty * 8 + 4];
            *(float4*)(bb)     = *(const float4*)&Bs[kk][tx * 4];
#pragma unroll
            for (int i = 0; i < 8; i++)
#pragma unroll
                for (int j = 0; j < 4; j++)
                    acc[i][j] += a[i] * bb[j];
        }
    }

#pragma unroll
    for (int i = 0; i < 8; i++) {
        int m = m0 + ty * 8 + i;
        int b = m >> 11, nr = m & (Nc - 1);
#pragma unroll
        for (int j = 0; j < 4; j++) {
            int n = n0 + tx * 4 + j;
            int h = n >> 5, d = n & 31;
            float val = acc[i][j] + bias[n];
            if (blockIdx.z == 0)
                g_q[((size_t)(b * Hc + h) * Nc + nr) * DHc + d] = val;
            else if (blockIdx.z == 1)
                g_kt[((size_t)(b * Hc + h) * DHc + d) * Nc + nr] = val;
            else
                g_v[((size_t)(b * Hc + h) * Nc + nr) * DHc + d] = val;
        }
    }
}

// ---------------------------------------------------------------------------
// Kernel 2: attention, tf32 mma.sync (m16n8k8). Block = (h, q-tile, b),
// h fastest so concurrent heads share the mask tile in L2.
// Phase 1: S = Q K^T, K staged with register prefetch.
// Phase 2: softmax + vis (STG.128) + mask (double-buffered, LDS.128 consume).
// Phase 3: x = P V, V fragments LDG'd directly from L2-resident g_v.
// ---------------------------------------------------------------------------
__global__ void __launch_bounds__(512) attn_kernel(const float* __restrict__ mask,
                                                   float* __restrict__ vis)
{
    extern __shared__ float sm[];
    float* lg = sm;                       // [16][LGS]
    float* Qs = sm + 16 * LGS;            // [16][QSS]
    float* St = Qs + 16 * QSS;            // 16640 floats stage area

    int h  = blockIdx.x;
    int q0 = blockIdx.y * 16;
    int b  = blockIdx.z;
    int bh = b * Hc + h;
    const float* qp  = g_q  + (size_t)bh * Nc * DHc;
    const float* ktp = g_kt + (size_t)bh * DHc * Nc;
    const float* vp  = g_v  + (size_t)bh * Nc * DHc;
    const float* mbase = mask + (size_t)b * Nc * Nc;

    int tid  = threadIdx.x;
    int wid  = tid >> 5;
    int lane = tid & 31;
    int grp  = lane >> 2;                 // 0..7
    int tig  = lane & 3;                  // 0..3

    // stage Q tile (tf32-rounded, pre-scaled)
    {
        int q = tid >> 5, d = tid & 31;
        Qs[q * QSS + d] = to_tf32(qp[(size_t)q0 * DHc + tid] * SCALEF);
    }
    __syncthreads();

    // A fragments of Q (same for every warp): 4 k-steps x 4 regs
    unsigned aq[4][4];
#pragma unroll
    for (int s = 0; s < 4; s++) {
        int dc = s * 8 + tig;
        aq[s][0] = __float_as_uint(Qs[grp * QSS + dc]);
        aq[s][1] = __float_as_uint(Qs[(grp + 8) * QSS + dc]);
        aq[s][2] = __float_as_uint(Qs[grp * QSS + dc + 4]);
        aq[s][3] = __float_as_uint(Qs[(grp + 8) * QSS + dc + 4]);
    }

    // ---- Phase 1: S = Q K^T, 4 chunks of 512 k, register-prefetched ----
    {
        const float4* kt4 = (const float4*)ktp;
        float4 pre[8];
#pragma unroll
        for (int j = 0; j < 8; j++) {
            int idx = tid + j * 512;
            int d = idx >> 7, kk4 = idx & 127;
            pre[j] = kt4[(size_t)d * 512 + kk4];
        }

        for (int c = 0; c < 4; c++) {
            float4* St4 = (float4*)St;
#pragma unroll
            for (int j = 0; j < 8; j++) {
                int idx = tid + j * 512;
                int d = idx >> 7, kk4 = idx & 127;
                float4 v = pre[j];
                v.x = to_tf32(v.x); v.y = to_tf32(v.y);
                v.z = to_tf32(v.z); v.w = to_tf32(v.w);
                St4[d * 130 + kk4] = v;
            }
            if (c < 3) {
#pragma unroll
                for (int j = 0; j < 8; j++) {
                    int idx = tid + j * 512;
                    int d = idx >> 7, kk4 = idx & 127;
                    pre[j] = kt4[(size_t)d * 512 + (c + 1) * 128 + kk4];
                }
            }
            __syncthreads();

#pragma unroll
            for (int nt = 0; nt < 4; nt++) {
                int kb = wid * 32 + nt * 8;
                float d0 = 0.f, d1 = 0.f, d2 = 0.f, d3 = 0.f;
#pragma unroll
                for (int s = 0; s < 4; s++) {
                    int dr = s * 8 + tig;
                    unsigned b0 = __float_as_uint(St[dr * 520 + kb + grp]);
                    unsigned b1 = __float_as_uint(St[(dr + 4) * 520 + kb + grp]);
                    mma8(d0, d1, d2, d3, aq[s][0], aq[s][1], aq[s][2], aq[s][3], b0, b1);
                }
                int kg = c * 512 + kb + 2 * tig;
                *(float2*)&lg[grp * LGS + kg]       = make_float2(d0, d1);
                *(float2*)&lg[(grp + 8) * LGS + kg] = make_float2(d2, d3);
            }
            __syncthreads();
        }
    }

    // ---- Phase 2: softmax (warp = row) + vis + mask, double-buffered ----
    {
        float* row = lg + wid * LGS;

        float mx = -1e30f;
#pragma unroll
        for (int i = 0; i < 16; i++) {
            float4 r = *(const float4*)&row[i * 128 + lane * 4];
            mx = fmaxf(mx, fmaxf(fmaxf(r.x, r.y), fmaxf(r.z, r.w)));
        }
#pragma unroll
        for (int o = 16; o; o >>= 1) mx = fmaxf(mx, __shfl_xor_sync(0xffffffffu, mx, o));

        float s = 0.f;
#pragma unroll
        for (int i = 0; i < 16; i++) {
            float4 r = *(float4*)&row[i * 128 + lane * 4];
            r.x = __expf(r.x - mx); r.y = __expf(r.y - mx);
            r.z = __expf(r.z - mx); r.w = __expf(r.w - mx);
            *(float4*)&row[i * 128 + lane * 4] = r;
            s += r.x + r.y + r.z + r.w;
        }
#pragma unroll
        for (int o = 16; o; o >>= 1) s += __shfl_xor_sync(0xffffffffu, s, o);
        float inv = 1.f / s;
        float rmx = 1.f / __uint_as_float(g_rmaxb[b * Nc + q0 + wid]);

        float* visrow = vis + ((size_t)bh * Nc + q0 + wid) * Nc;

        int skk = tid >> 1;                 // 0..255
        int sc8 = (tid & 1) * 8;            // 0 or 8
        const float* mp0 = mbase + (size_t)skk * Nc + q0 + sc8;
        float4 a0 = ((const float4*)mp0)[0];
        float4 a1 = ((const float4*)mp0)[1];

        for (int ch = 0; ch < 8; ch++) {
            float* Sb = St + (ch & 1) * 4160;           // [16 q][MSS]
            Sb[(sc8 + 0) * MSS + skk] = a0.x;
            Sb[(sc8 + 1) * MSS + skk] = a0.y;
            Sb[(sc8 + 2) * MSS + skk] = a0.z;
            Sb[(sc8 + 3) * MSS + skk] = a0.w;
            Sb[(sc8 + 4) * MSS + skk] = a1.x;
            Sb[(sc8 + 5) * MSS + skk] = a1.y;
            Sb[(sc8 + 6) * MSS + skk] = a1.z;
            Sb[(sc8 + 7) * MSS + skk] = a1.w;
            if (ch < 7) {
                const float* mn = mbase + (size_t)((ch + 1) * 256 + skk) * Nc + q0 + sc8;
                a0 = ((const float4*)mn)[0];
                a1 = ((const float4*)mn)[1];
            }
            __syncthreads();

#pragma unroll
            for (int i = 0; i < 2; i++) {
                int kk = i * 128 + lane * 4;
                int k  = ch * 256 + kk;
                float4 e = *(const float4*)&row[k];
                float4 p = make_float4(e.x * inv, e.y * inv, e.z * inv, e.w * inv);
                *(float4*)&visrow[k] = p;                      // pre-mask prob, STG.128
                float4 m4 = *(const float4*)&Sb[wid * MSS + kk];
                p.x = to_tf32(p.x * m4.x * rmx);
                p.y = to_tf32(p.y * m4.y * rmx);
                p.z = to_tf32(p.z * m4.z * rmx);
                p.w = to_tf32(p.w * m4.w * rmx);
                *(float4*)&row[k] = p;                         // masked tf32 P
            }
            // no trailing sync: double-buffered; next chunk's barrier protects reuse
        }
    }
    __syncthreads();

    // ---- Phase 3: x = P V.  warp = (d-tile, k-quarter). V LDG'd from L2. ----
    {
        int dt = (wid & 3) * 8;             // d-tile base
        int kq = wid >> 2;                  // k quarter (512 k each)
        float x0 = 0.f, x1 = 0.f, x2 = 0.f, x3 = 0.f;

#pragma unroll 4
        for (int s2 = 0; s2 < 64; s2++) {
            int kg = kq * 512 + s2 * 8;
            unsigned a0 = __float_as_uint(lg[grp * LGS + kg + tig]);
            unsigned a1 = __float_as_uint(lg[(grp + 8) * LGS + kg + tig]);
            unsigned a2 = __float_as_uint(lg[grp * LGS + kg + tig + 4]);
            unsigned a3 = __float_as_uint(lg[(grp + 8) * LGS + kg + tig + 4]);
            unsigned b0 = __float_as_uint(to_tf32(vp[(size_t)(kg + tig) * DHc + dt + grp]));
            unsigned b1 = __float_as_uint(to_tf32(vp[(size_t)(kg + tig + 4) * DHc + dt + grp]));
            mma8(x0, x1, x2, x3, a0, a1, a2, a3, b0, b1);
        }

        // cross-warp combine over the 4 k-quarters: St[(kq*16 + q)*33 + d]
        St[(kq * 16 + grp) * 33 + dt + 2 * tig]     = x0;
        St[(kq * 16 + grp) * 33 + dt + 2 * tig + 1] = x1;
        St[(kq * 16 + grp + 8) * 33 + dt + 2 * tig]     = x2;
        St[(kq * 16 + grp + 8) * 33 + dt + 2 * tig + 1] = x3;
        __syncthreads();

        int q = tid >> 5, d = tid & 31;
        float x = St[q * 33 + d] + St[(16 + q) * 33 + d]
                + St[(32 + q) * 33 + d] + St[(48 + q) * 33 + d];
        g_x[((size_t)(b * Nc + q0 + q)) * Cc + h * 32 + d] = x;
    }
}

// ---------------------------------------------------------------------------
// Kernel 3: output projection + residual. 128x64 tile, 8x4 microtile.
// ---------------------------------------------------------------------------
__global__ void __launch_bounds__(256) oproj_kernel(
    const float* __restrict__ Wo, const float* __restrict__ bo,
    const float* __restrict__ query, float* __restrict__ out)
{
    __shared__ float As[8][132];
    __shared__ float Bs[8][68];

    int m0 = blockIdx.x * 128;
    int n0 = blockIdx.y * 64;
    int tid = threadIdx.x;
    int ty = tid >> 4, tx = tid & 15;
    int lr = tid >> 1;
    int lf = (tid & 1) * 4;

    float acc[8][4];
#pragma unroll
    for (int i = 0; i < 8; i++)
#pragma unroll
        for (int j = 0; j < 4; j++) acc[i][j] = 0.f;

    for (int k0 = 0; k0 < Cc; k0 += 8) {
        float4 xa = *(const float4*)(g_x + (size_t)(m0 + lr) * Cc + k0 + lf);
        float4 wb;
        if (tid < 128)
            wb = *(const float4*)(Wo + (size_t)(n0 + lr) * Cc + k0 + lf);
        __syncthreads();
        As[lf + 0][lr] = xa.x; As[lf + 1][lr] = xa.y; As[lf + 2][lr] = xa.z; As[lf + 3][lr] = xa.w;
        if (tid < 128) {
            Bs[lf + 0][lr] = wb.x; Bs[lf + 1][lr] = wb.y;
            Bs[lf + 2][lr] = wb.z; Bs[lf + 3][lr] = wb.w;
        }
        __syncthreads();
#pragma unroll
        for (int kk = 0; kk < 8; kk++) {
            float a[8], bb[4];
            *(float4*)(a)      = *(const float4*)&As[kk][ty * 8];
            *(float4*)(a + 4)  = *(const float4*)&As[kk][ty * 8 + 4];
            *(float4*)(bb)     = *(const float4*)&Bs[kk][tx * 4];
#pragma unroll
            for (int i = 0; i < 8; i++)
#pragma unroll
                for (int j = 0; j < 4; j++)
                    acc[i][j] += a[i] * bb[j];
        }
    }

#pragma unroll
    for (int i = 0; i < 8; i++) {
        int m = m0 + ty * 8 + i;
#pragma unroll
        for (int j = 0; j < 4; j++) {
            int n = n0 + tx * 4 + j;
            out[(size_t)m * Cc + n] = acc[i][j] + query[(size_t)m * Cc + n] + bo[n];
        }
    }
}

// ---------------------------------------------------------------------------
extern "C" void kernel_launch(void* const* d_in, const int* in_sizes, int n_in,
                              void* d_out, int out_size)
{
    const float* query = (const float*)d_in[0];
    const float* mask  = (const float*)d_in[1];
    const float* Wq = (const float*)d_in[2];
    const float* bq = (const float*)d_in[3];
    const float* Wk = (const float*)d_in[4];
    const float* bk = (const float*)d_in[5];
    const float* Wv = (const float*)d_in[6];
    const float* bv = (const float*)d_in[7];
    const float* Wo = (const float*)d_in[8];
    const float* bo = (const float*)d_in[9];

    float* out_query = (float*)d_out;                       // [B,N,C]
    float* vis       = out_query + (size_t)Bc * Nc * Cc;    // [B,H,N,N]

    dim3 gr(Nc / 256, Nc / 256, Bc);
    rmax_kernel<<<gr, 256>>>(mask);

    dim3 gq((Bc * Nc) / 128, Cc / 64, 3);
    qkv_kernel<<<gq, 256>>>(query, Wq, Wk, Wv, bq, bk, bv);

    size_t smem = (size_t)(16 * LGS + 16 * QSS + 16640) * sizeof(float); // 200448 B
    cudaFuncSetAttribute(attn_kernel, cudaFuncAttributeMaxDynamicSharedMemorySize, (int)smem);
    dim3 ga(Hc, Nc / 16, Bc);   // h fastest -> mask tile shared in L2
    attn_kernel<<<ga, 512, smem>>>(mask, vis);

    dim3 go((Bc * Nc) / 128, Cc / 64);
    oproj_kernel<<<go, 256>>>(Wo, bo, query, out_query);
}

// round 7
// speedup vs baseline: 3.6930x; 1.4775x over previous
#include <cuda_runtime.h>
#include <cuda_fp16.h>
#include <cstdint>

#define Bc 4
#define Nc 2048
#define Cc 256
#define Hc 8
#define DHc 32
#define SCALEF 0.17677669529663687f   // 32^-0.5
#define LGS 2056                      // lg row stride (floats)
#define MSS 260                       // mask stage row stride (floats)
#define KSS 40                        // K/Q stage row stride (halfs)

// ---- scratch (static device allocations) ----
__device__ __half g_qh [Bc*Hc*Nc*DHc];   // Q [bh][n][d], pre-scaled by SCALEF
__device__ __half g_kh [Bc*Hc*Nc*DHc];   // K [bh][n][d]
__device__ __half g_vth[Bc*Hc*DHc*Nc];   // V transposed [bh][d][n]
__device__ float  g_x  [Bc*Nc*Cc];       // attention output [B*N, C]
__device__ unsigned int g_rmaxb[Bc*Nc];  // max_k mask[b,k,q] as monotone uint bits

// ---- MMA helpers ----
__device__ __forceinline__ float to_tf32(float x) {
    unsigned u;
    asm("cvt.rna.tf32.f32 %0, %1;" : "=r"(u) : "f"(x));
    return __uint_as_float(u);
}
__device__ __forceinline__ void mma8(float& d0, float& d1, float& d2, float& d3,
                                     unsigned a0, unsigned a1, unsigned a2, unsigned a3,
                                     unsigned b0, unsigned b1) {
    asm volatile(
        "mma.sync.aligned.m16n8k8.row.col.f32.tf32.tf32.f32 "
        "{%0,%1,%2,%3},{%4,%5,%6,%7},{%8,%9},{%0,%1,%2,%3};"
        : "+f"(d0), "+f"(d1), "+f"(d2), "+f"(d3)
        : "r"(a0), "r"(a1), "r"(a2), "r"(a3), "r"(b0), "r"(b1));
}
__device__ __forceinline__ void mma16(float& d0, float& d1, float& d2, float& d3,
                                      unsigned a0, unsigned a1, unsigned a2, unsigned a3,
                                      unsigned b0, unsigned b1) {
    asm volatile(
        "mma.sync.aligned.m16n8k16.row.col.f32.f16.f16.f32 "
        "{%0,%1,%2,%3},{%4,%5,%6,%7},{%8,%9},{%0,%1,%2,%3};"
        : "+f"(d0), "+f"(d1), "+f"(d2), "+f"(d3)
        : "r"(a0), "r"(a1), "r"(a2), "r"(a3), "r"(b0), "r"(b1));
}
__device__ __forceinline__ unsigned pack_h2(float lo, float hi) {
    __half2 h = __floats2half2_rn(lo, hi);
    return *(unsigned*)&h;
}

// ---------------------------------------------------------------------------
// Kernel 0: column-max of mask via atomicMax on float bits (mask > 0).
// ---------------------------------------------------------------------------
__global__ void __launch_bounds__(256) rmax_kernel(const float* __restrict__ mask)
{
    int q  = blockIdx.x * 256 + threadIdx.x;
    int k0 = blockIdx.y * 256;
    int b  = blockIdx.z;
    const float* mc = mask + (size_t)b * Nc * Nc + q;
    float mx = 0.f;
#pragma unroll 8
    for (int k = 0; k < 256; k++)
        mx = fmaxf(mx, mc[(size_t)(k0 + k) * Nc]);
    atomicMax(&g_rmaxb[b * Nc + q], __float_as_uint(mx));
}

// ---------------------------------------------------------------------------
// Kernel 1: QKV projection via tf32 MMA. Tile 32m x 64n, 8 warps.
// Writes half outputs: Q (pre-scaled), K row-major, V transposed.
// ---------------------------------------------------------------------------
__global__ void __launch_bounds__(256) qkv_mma_kernel(
    const float* __restrict__ X,
    const float* __restrict__ Wq, const float* __restrict__ Wk, const float* __restrict__ Wv,
    const float* __restrict__ bq, const float* __restrict__ bk, const float* __restrict__ bv)
{
    __shared__ float As[32][36];
    __shared__ float Bs[64][36];
    __shared__ float bias_s[64];

    const float* W; const float* bias;
    if (blockIdx.z == 0)      { W = Wq; bias = bq; }
    else if (blockIdx.z == 1) { W = Wk; bias = bk; }
    else                      { W = Wv; bias = bv; }

    int m0 = blockIdx.x * 32;
    int n0 = blockIdx.y * 64;
    int tid = threadIdx.x;
    int wid = tid >> 5, lane = tid & 31;
    int grp = lane >> 2, tig = lane & 3;
    int mw = wid >> 2, nw = wid & 3;

    if (tid < 64) bias_s[tid] = bias[n0 + tid];

    float acc[2][4];
#pragma unroll
    for (int i = 0; i < 2; i++)
#pragma unroll
        for (int j = 0; j < 4; j++) acc[i][j] = 0.f;

    int arow = tid >> 3, aseg = tid & 7;

    for (int c = 0; c < 8; c++) {
        float4 xa = *(const float4*)(X + (size_t)(m0 + arow) * Cc + c * 32 + aseg * 4);
        float4 wb0 = *(const float4*)(W + (size_t)(n0 + arow) * Cc + c * 32 + aseg * 4);
        float4 wb1 = *(const float4*)(W + (size_t)(n0 + 32 + arow) * Cc + c * 32 + aseg * 4);
        __syncthreads();
        xa.x = to_tf32(xa.x); xa.y = to_tf32(xa.y); xa.z = to_tf32(xa.z); xa.w = to_tf32(xa.w);
        *(float4*)&As[arow][aseg * 4] = xa;
        wb0.x = to_tf32(wb0.x); wb0.y = to_tf32(wb0.y); wb0.z = to_tf32(wb0.z); wb0.w = to_tf32(wb0.w);
        *(float4*)&Bs[arow][aseg * 4] = wb0;
        wb1.x = to_tf32(wb1.x); wb1.y = to_tf32(wb1.y); wb1.z = to_tf32(wb1.z); wb1.w = to_tf32(wb1.w);
        *(float4*)&Bs[32 + arow][aseg * 4] = wb1;
        __syncthreads();

#pragma unroll
        for (int s = 0; s < 4; s++) {
            unsigned a0 = __float_as_uint(As[mw * 16 + grp][s * 8 + tig]);
            unsigned a1 = __float_as_uint(As[mw * 16 + grp + 8][s * 8 + tig]);
            unsigned a2 = __float_as_uint(As[mw * 16 + grp][s * 8 + tig + 4]);
            unsigned a3 = __float_as_uint(As[mw * 16 + grp + 8][s * 8 + tig + 4]);
#pragma unroll
            for (int nt = 0; nt < 2; nt++) {
                unsigned b0 = __float_as_uint(Bs[nw * 16 + nt * 8 + grp][s * 8 + tig]);
                unsigned b1 = __float_as_uint(Bs[nw * 16 + nt * 8 + grp][s * 8 + tig + 4]);
                mma8(acc[nt][0], acc[nt][1], acc[nt][2], acc[nt][3], a0, a1, a2, a3, b0, b1);
            }
        }
    }

    // epilogue
#pragma unroll
    for (int nt = 0; nt < 2; nt++) {
        int cn = n0 + nw * 16 + nt * 8;
        int c0 = cn + 2 * tig;
#pragma unroll
        for (int rr = 0; rr < 2; rr++) {
            int m = m0 + mw * 16 + grp + rr * 8;
            int b = m >> 11, nr = m & (Nc - 1);
            float v0 = acc[nt][rr * 2 + 0] + bias_s[c0 - n0];
            float v1 = acc[nt][rr * 2 + 1] + bias_s[c0 - n0 + 1];
            int h = c0 >> 5, d = c0 & 31;
            size_t bh = (size_t)(b * Hc + h);
            if (blockIdx.z == 0) {
                __half2 hv = __floats2half2_rn(v0 * SCALEF, v1 * SCALEF);
                *(__half2*)&g_qh[(bh * Nc + nr) * DHc + d] = hv;
            } else if (blockIdx.z == 1) {
                __half2 hv = __floats2half2_rn(v0, v1);
                *(__half2*)&g_kh[(bh * Nc + nr) * DHc + d] = hv;
            } else {
                g_vth[(bh * DHc + d) * Nc + nr]     = __float2half_rn(v0);
                g_vth[(bh * DHc + d + 1) * Nc + nr] = __float2half_rn(v1);
            }
        }
    }
}

// ---------------------------------------------------------------------------
// Kernel 2: attention, fp16 mma.sync (m16n8k16). Block = (h, q-tile, b).
// Phase 1: S = Q K^T, K staged as half rows (register prefetch).
// Phase 2: softmax fp32 + vis STG.128 + mask (double-buffered);
//          P compacted fp32->half IN PLACE inside lg (skewed per row).
// Phase 3: x = P V via fp16 MMA, V^T fragments LDG'd as half2 from L2.
// Smem: lg 16*2056*4 + Qs 16*40*2 + St 40960 = 173,824 B.
// ---------------------------------------------------------------------------
__global__ void __launch_bounds__(512) attn_kernel(const float* __restrict__ mask,
                                                   float* __restrict__ vis)
{
    extern __shared__ float sm[];
    float* lg = sm;                       // [16][LGS] fp32 logits -> fp16 P (packed)
    __half* Qsh = (__half*)(sm + 16 * LGS);       // [16][KSS]
    float* St = sm + 16 * LGS + (16 * KSS) / 2;   // stage area (floats view)
    __half* Sth = (__half*)St;                    // half view for K staging

    int h  = blockIdx.x;
    int q0 = blockIdx.y * 16;
    int b  = blockIdx.z;
    int bh = b * Hc + h;
    const __half* qhp  = g_qh  + (size_t)bh * Nc * DHc;
    const __half* khp  = g_kh  + (size_t)bh * Nc * DHc;
    const __half* vthp = g_vth + (size_t)bh * DHc * Nc;
    const float* mbase = mask + (size_t)b * Nc * Nc;

    int tid  = threadIdx.x;
    int wid  = tid >> 5;
    int lane = tid & 31;
    int grp  = lane >> 2;                 // 0..7
    int tig  = lane & 3;                  // 0..3

    // stage Q tile (already scaled + half in g_qh)
    if (tid < 256) {
        int q = tid >> 4, dp = tid & 15;
        unsigned v = ((const unsigned*)qhp)[q0 * 16 + tid];
        *(unsigned*)&Qsh[q * KSS + dp * 2] = v;
    }
    __syncthreads();

    // A fragments of Q: 2 k16-steps x 4 regs
    unsigned aq[2][4];
#pragma unroll
    for (int s = 0; s < 2; s++) {
        aq[s][0] = *(const unsigned*)&Qsh[grp * KSS + s * 16 + 2 * tig];
        aq[s][1] = *(const unsigned*)&Qsh[(grp + 8) * KSS + s * 16 + 2 * tig];
        aq[s][2] = *(const unsigned*)&Qsh[grp * KSS + s * 16 + 2 * tig + 8];
        aq[s][3] = *(const unsigned*)&Qsh[(grp + 8) * KSS + s * 16 + 2 * tig + 8];
    }

    // ---- Phase 1: S = Q K^T, 4 chunks of 512 k, register-prefetched ----
    {
        const uint4* kh4 = (const uint4*)khp;     // 16B = 8 halfs; 4 per k-row
        uint4 pre[4];
#pragma unroll
        for (int j = 0; j < 4; j++) {
            int idx = tid + j * 512;
            pre[j] = kh4[idx];                    // row=idx>>2, seg=idx&3
        }

        for (int c = 0; c < 4; c++) {
#pragma unroll
            for (int j = 0; j < 4; j++) {
                int idx = tid + j * 512;
                int row = idx >> 2, seg = idx & 3;
                *(uint4*)&Sth[row * KSS + seg * 8] = pre[j];
            }
            if (c < 3) {
#pragma unroll
                for (int j = 0; j < 4; j++) {
                    int idx = tid + j * 512;
                    pre[j] = kh4[(c + 1) * 2048 + idx];
                }
            }
            __syncthreads();

#pragma unroll
            for (int nt = 0; nt < 4; nt++) {
                int kb = wid * 32 + nt * 8;
                float d0 = 0.f, d1 = 0.f, d2 = 0.f, d3 = 0.f;
#pragma unroll
                for (int s = 0; s < 2; s++) {
                    unsigned b0 = *(const unsigned*)&Sth[(kb + grp) * KSS + s * 16 + 2 * tig];
                    unsigned b1 = *(const unsigned*)&Sth[(kb + grp) * KSS + s * 16 + 2 * tig + 8];
                    mma16(d0, d1, d2, d3, aq[s][0], aq[s][1], aq[s][2], aq[s][3], b0, b1);
                }
                int kg = c * 512 + kb + 2 * tig;
                *(float2*)&lg[grp * LGS + kg]       = make_float2(d0, d1);
                *(float2*)&lg[(grp + 8) * LGS + kg] = make_float2(d2, d3);
            }
            __syncthreads();
        }
    }

    // ---- Phase 2: softmax (warp = row) + vis + mask; P -> half in place ----
    {
        float* row = lg + wid * LGS;
        __half* hrow = (__half*)((char*)(lg) + (size_t)wid * LGS * 4 + (wid & 7) * 16);

        float mx = -1e30f;
#pragma unroll
        for (int i = 0; i < 16; i++) {
            float4 r = *(const float4*)&row[i * 128 + lane * 4];
            mx = fmaxf(mx, fmaxf(fmaxf(r.x, r.y), fmaxf(r.z, r.w)));
        }
#pragma unroll
        for (int o = 16; o; o >>= 1) mx = fmaxf(mx, __shfl_xor_sync(0xffffffffu, mx, o));

        float s = 0.f;
#pragma unroll
        for (int i = 0; i < 16; i++) {
            float4 r = *(float4*)&row[i * 128 + lane * 4];
            r.x = __expf(r.x - mx); r.y = __expf(r.y - mx);
            r.z = __expf(r.z - mx); r.w = __expf(r.w - mx);
            *(float4*)&row[i * 128 + lane * 4] = r;
            s += r.x + r.y + r.z + r.w;
        }
#pragma unroll
        for (int o = 16; o; o >>= 1) s += __shfl_xor_sync(0xffffffffu, s, o);
        float inv = 1.f / s;
        float rmx = 1.f / __uint_as_float(g_rmaxb[b * Nc + q0 + wid]);

        float* visrow = vis + ((size_t)bh * Nc + q0 + wid) * Nc;

        int skk = tid >> 1;                 // 0..255
        int sc8 = (tid & 1) * 8;            // 0 or 8
        const float* mp0 = mbase + (size_t)skk * Nc + q0 + sc8;
        float4 a0 = ((const float4*)mp0)[0];
        float4 a1 = ((const float4*)mp0)[1];

        for (int ch = 0; ch < 8; ch++) {
            float* Sb = St + (ch & 1) * 4160;           // [16 q][MSS]
            Sb[(sc8 + 0) * MSS + skk] = a0.x;
            Sb[(sc8 + 1) * MSS + skk] = a0.y;
            Sb[(sc8 + 2) * MSS + skk] = a0.z;
            Sb[(sc8 + 3) * MSS + skk] = a0.w;
            Sb[(sc8 + 4) * MSS + skk] = a1.x;
            Sb[(sc8 + 5) * MSS + skk] = a1.y;
            Sb[(sc8 + 6) * MSS + skk] = a1.z;
            Sb[(sc8 + 7) * MSS + skk] = a1.w;
            if (ch < 7) {
                const float* mn = mbase + (size_t)((ch + 1) * 256 + skk) * Nc + q0 + sc8;
                a0 = ((const float4*)mn)[0];
                a1 = ((const float4*)mn)[1];
            }
            __syncthreads();

#pragma unroll
            for (int i = 0; i < 2; i++) {
                int kk = i * 128 + lane * 4;
                int k  = ch * 256 + kk;
                float4 e = *(const float4*)&row[k];
                float4 p = make_float4(e.x * inv, e.y * inv, e.z * inv, e.w * inv);
                *(float4*)&visrow[k] = p;                      // pre-mask prob
                float4 m4 = *(const float4*)&Sb[wid * MSS + kk];
                unsigned h0 = pack_h2(p.x * m4.x * rmx, p.y * m4.y * rmx);
                unsigned h1 = pack_h2(p.z * m4.z * rmx, p.w * m4.w * rmx);
                uint2 w = make_uint2(h0, h1);
                *(uint2*)&hrow[k] = w;                         // in-place half P
            }
        }
    }
    __syncthreads();

    // ---- Phase 3: x = P V via fp16 MMA. warp = (d-tile, k-quarter) ----
    {
        int dt = (wid & 3) * 8;             // d-tile base
        int kq = wid >> 2;                  // k quarter (512 k each)
        float x0 = 0.f, x1 = 0.f, x2 = 0.f, x3 = 0.f;

        const __half* hg0 = (const __half*)((char*)(lg) + (size_t)grp * LGS * 4 + (grp & 7) * 16);
        const __half* hg1 = (const __half*)((char*)(lg) + (size_t)(grp + 8) * LGS * 4 + (grp & 7) * 16);

#pragma unroll 4
        for (int s2 = 0; s2 < 32; s2++) {
            int k0 = kq * 512 + s2 * 16;
            unsigned a0 = *(const unsigned*)&hg0[k0 + 2 * tig];
            unsigned a1 = *(const unsigned*)&hg1[k0 + 2 * tig];
            unsigned a2 = *(const unsigned*)&hg0[k0 + 2 * tig + 8];
            unsigned a3 = *(const unsigned*)&hg1[k0 + 2 * tig + 8];
            unsigned b0 = *(const unsigned*)&vthp[(size_t)(dt + grp) * Nc + k0 + 2 * tig];
            unsigned b1 = *(const unsigned*)&vthp[(size_t)(dt + grp) * Nc + k0 + 2 * tig + 8];
            mma16(x0, x1, x2, x3, a0, a1, a2, a3, b0, b1);
        }

        // cross-warp combine over the 4 k-quarters
        St[(kq * 16 + grp) * 33 + dt + 2 * tig]     = x0;
        St[(kq * 16 + grp) * 33 + dt + 2 * tig + 1] = x1;
        St[(kq * 16 + grp + 8) * 33 + dt + 2 * tig]     = x2;
        St[(kq * 16 + grp + 8) * 33 + dt + 2 * tig + 1] = x3;
        __syncthreads();

        int q = tid >> 5, d = tid & 31;
        float x = St[q * 33 + d] + St[(16 + q) * 33 + d]
                + St[(32 + q) * 33 + d] + St[(48 + q) * 33 + d];
        g_x[((size_t)(b * Nc + q0 + q)) * Cc + h * 32 + d] = x;
    }
}

// ---------------------------------------------------------------------------
// Kernel 3: output projection + residual via tf32 MMA. Tile 32m x 64n.
// ---------------------------------------------------------------------------
__global__ void __launch_bounds__(256) oproj_mma_kernel(
    const float* __restrict__ Wo, const float* __restrict__ bo,
    const float* __restrict__ query, float* __restrict__ out)
{
    __shared__ float As[32][36];
    __shared__ float Bs[64][36];
    __shared__ float bias_s[64];

    int m0 = blockIdx.x * 32;
    int n0 = blockIdx.y * 64;
    int tid = threadIdx.x;
    int wid = tid >> 5, lane = tid & 31;
    int grp = lane >> 2, tig = lane & 3;
    int mw = wid >> 2, nw = wid & 3;

    if (tid < 64) bias_s[tid] = bo[n0 + tid];

    float acc[2][4];
#pragma unroll
    for (int i = 0; i < 2; i++)
#pragma unroll
        for (int j = 0; j < 4; j++) acc[i][j] = 0.f;

    int arow = tid >> 3, aseg = tid & 7;

    for (int c = 0; c < 8; c++) {
        float4 xa = *(const float4*)(g_x + (size_t)(m0 + arow) * Cc + c * 32 + aseg * 4);
        float4 wb0 = *(const float4*)(Wo + (size_t)(n0 + arow) * Cc + c * 32 + aseg * 4);
        float4 wb1 = *(const float4*)(Wo + (size_t)(n0 + 32 + arow) * Cc + c * 32 + aseg * 4);
        __syncthreads();
        xa.x = to_tf32(xa.x); xa.y = to_tf32(xa.y); xa.z = to_tf32(xa.z); xa.w = to_tf32(xa.w);
        *(float4*)&As[arow][aseg * 4] = xa;
        wb0.x = to_tf32(wb0.x); wb0.y = to_tf32(wb0.y); wb0.z = to_tf32(wb0.z); wb0.w = to_tf32(wb0.w);
        *(float4*)&Bs[arow][aseg * 4] = wb0;
        wb1.x = to_tf32(wb1.x); wb1.y = to_tf32(wb1.y); wb1.z = to_tf32(wb1.z); wb1.w = to_tf32(wb1.w);
        *(float4*)&Bs[32 + arow][aseg * 4] = wb1;
        __syncthreads();

#pragma unroll
        for (int s = 0; s < 4; s++) {
            unsigned a0 = __float_as_uint(As[mw * 16 + grp][s * 8 + tig]);
            unsigned a1 = __float_as_uint(As[mw * 16 + grp + 8][s * 8 + tig]);
            unsigned a2 = __float_as_uint(As[mw * 16 + grp][s * 8 + tig + 4]);
            unsigned a3 = __float_as_uint(As[mw * 16 + grp + 8][s * 8 + tig + 4]);
#pragma unroll
            for (int nt = 0; nt < 2; nt++) {
                unsigned b0 = __float_as_uint(Bs[nw * 16 + nt * 8 + grp][s * 8 + tig]);
                unsigned b1 = __float_as_uint(Bs[nw * 16 + nt * 8 + grp][s * 8 + tig + 4]);
                mma8(acc[nt][0], acc[nt][1], acc[nt][2], acc[nt][3], a0, a1, a2, a3, b0, b1);
            }
        }
    }

#pragma unroll
    for (int nt = 0; nt < 2; nt++) {
        int c0 = n0 + nw * 16 + nt * 8 + 2 * tig;
#pragma unroll
        for (int rr = 0; rr < 2; rr++) {
            int m = m0 + mw * 16 + grp + rr * 8;
            float2 qv = *(const float2*)&query[(size_t)m * Cc + c0];
            float2 ov;
            ov.x = acc[nt][rr * 2 + 0] + bias_s[c0 - n0]     + qv.x;
            ov.y = acc[nt][rr * 2 + 1] + bias_s[c0 - n0 + 1] + qv.y;
            *(float2*)&out[(size_t)m * Cc + c0] = ov;
        }
    }
}

// ---------------------------------------------------------------------------
extern "C" void kernel_launch(void* const* d_in, const int* in_sizes, int n_in,
                              void* d_out, int out_size)
{
    const float* query = (const float*)d_in[0];
    const float* mask  = (const float*)d_in[1];
    const float* Wq = (const float*)d_in[2];
    const float* bq = (const float*)d_in[3];
    const float* Wk = (const float*)d_in[4];
    const float* bk = (const float*)d_in[5];
    const float* Wv = (const float*)d_in[6];
    const float* bv = (const float*)d_in[7];
    const float* Wo = (const float*)d_in[8];
    const float* bo = (const float*)d_in[9];

    float* out_query = (float*)d_out;                       // [B,N,C]
    float* vis       = out_query + (size_t)Bc * Nc * Cc;    // [B,H,N,N]

    dim3 gr(Nc / 256, Nc / 256, Bc);
    rmax_kernel<<<gr, 256>>>(mask);

    dim3 gq((Bc * Nc) / 32, Cc / 64, 3);
    qkv_mma_kernel<<<gq, 256>>>(query, Wq, Wk, Wv, bq, bk, bv);

    size_t smem = (size_t)(16 * LGS * 4 + 16 * KSS * 2 + 40960); // 173,824 B
    cudaFuncSetAttribute(attn_kernel, cudaFuncAttributeMaxDynamicSharedMemorySize, (int)smem);
    dim3 ga(Hc, Nc / 16, Bc);   // h fastest -> mask tile shared in L2
    attn_kernel<<<ga, 512, smem>>>(mask, vis);

    dim3 go((Bc * Nc) / 32, Cc / 64);
    oproj_mma_kernel<<<go, 256>>>(Wo, bo, query, out_query);
}